// round 14
// baseline (speedup 1.0000x reference)
#include <cuda_runtime.h>
#include <cuda_fp16.h>
#include <math.h>
#include <stdint.h>
#include <mma.h>

using namespace nvcuda;

#define F 128
#define NMAX 100000
#define EMAX 1600000
#define BGR 8
#define CAPD 96
#define BKP 48

// ---------------- device scratch ----------------
__device__ float  g_y[NMAX * F];
__device__ float  g_h1[NMAX * F];
__device__ __half g_xh[NMAX * F];
__device__ __half g_xl[NMAX * F];
__device__ __half g_ah[NMAX * F];
__device__ __half g_al[NMAX * F];
__device__ __half g_w1h[128 * 128];
__device__ __half g_w1l[128 * 128];
__device__ __half g_w2h[128 * 256];
__device__ __half g_w2l[128 * 256];
__device__ int    g_npA[NMAX + 1];   // stage0 nodes -> stage1 ids (dummy 80000)
__device__ int    g_npB[80001];      // stage1 nodes -> stage2 ids (dummy 64000)
__device__ int    g_npC[NMAX + 1];   // composed: stage0 -> stage2
__device__ int    g_deg[NMAX];
__device__ int    g_bkt[NMAX * CAPD];
__device__ float  g_s[NMAX];
__device__ int    g_gidx[80000];
__device__ float  g_tanhv[80000];
__device__ unsigned g_thr[BGR];
__device__ int    g_needeq[BGR];
__device__ int    g_cnt[BGR];
__device__ int    g_eqcnt[BGR];
__device__ float  g_z[BGR * 2 * F];
__device__ float  g_part[10000 * 2 * F];   // per-gather-block partials (max Mn/8 = 10000)

__device__ __forceinline__ unsigned ordkey(float f) {
    unsigned u = __float_as_uint(f);
    return (u & 0x80000000u) ? ~u : (u | 0x80000000u);
}

__device__ __forceinline__ void split2(float v, __half& h, __half& l) {
    h = __float2half_rn(v);
    l = __float2half_rn(v - __half2float(h));
}

__device__ __forceinline__ void cp16(uint32_t saddr, const void* gptr, bool valid) {
    int sz = valid ? 16 : 0;
    asm volatile("cp.async.cg.shared.global [%0], [%1], 16, %2;"
                 :: "r"(saddr), "l"(gptr), "r"(sz));
}
#define CP_COMMIT() asm volatile("cp.async.commit_group;" ::: "memory")
#define CP_WAIT1()  asm volatile("cp.async.wait_group 1;" ::: "memory")
#define CP_WAIT0()  asm volatile("cp.async.wait_group 0;" ::: "memory")

// ---------------- stage-0 input split ----------------
__global__ void k_split(const float* __restrict__ src, __half* __restrict__ hi,
                        __half* __restrict__ lo, int n4)
{
    int i = blockIdx.x * blockDim.x + threadIdx.x;
    if (i >= n4) return;
    float4 v = ((const float4*)src)[i];
    __half h0, h1, h2, h3, l0, l1, l2, l3;
    split2(v.x, h0, l0); split2(v.y, h1, l1);
    split2(v.z, h2, l2); split2(v.w, h3, l3);
    ((__half2*)hi)[i * 2 + 0] = __halves2half2(h0, h1);
    ((__half2*)hi)[i * 2 + 1] = __halves2half2(h2, h3);
    ((__half2*)lo)[i * 2 + 0] = __halves2half2(l0, l1);
    ((__half2*)lo)[i * 2 + 1] = __halves2half2(l2, l3);
}

// ---------------- per-stage prep: deg zero + weight splits ----------------
__global__ void k_prep(const float* __restrict__ W1, const float* __restrict__ W2, int M)
{
    int i = blockIdx.x * blockDim.x + threadIdx.x;
    if (i < M) g_deg[i] = 0;
    const int n1 = 128 * 128 / 4;
    const int n2 = 128 * 256 / 4;
    if (i < n1) {
        float4 v = ((const float4*)W1)[i];
        __half h0, h1, h2, h3, l0, l1, l2, l3;
        split2(v.x, h0, l0); split2(v.y, h1, l1);
        split2(v.z, h2, l2); split2(v.w, h3, l3);
        ((__half2*)g_w1h)[i * 2 + 0] = __halves2half2(h0, h1);
        ((__half2*)g_w1h)[i * 2 + 1] = __halves2half2(h2, h3);
        ((__half2*)g_w1l)[i * 2 + 0] = __halves2half2(l0, l1);
        ((__half2*)g_w1l)[i * 2 + 1] = __halves2half2(l2, l3);
    } else if (i < n1 + n2) {
        int idx = i - n1;
        float4 v = ((const float4*)W2)[idx];
        __half h0, h1, h2, h3, l0, l1, l2, l3;
        split2(v.x, h0, l0); split2(v.y, h1, l1);
        split2(v.z, h2, l2); split2(v.w, h3, l3);
        ((__half2*)g_w2h)[idx * 2 + 0] = __halves2half2(h0, h1);
        ((__half2*)g_w2h)[idx * 2 + 1] = __halves2half2(h2, h3);
        ((__half2*)g_w2l)[idx * 2 + 0] = __halves2half2(l0, l1);
        ((__half2*)g_w2l)[idx * 2 + 1] = __halves2half2(l2, l3);
    }
}

// ---------------- fp16-split wmma GEMM with cp.async double buffering ----------------
#define STG_B 12288
#define STAGE_B (4 * STG_B)
#define SMEM_H (2 * STAGE_B + 8192)

template <int KPARTS>
__global__ __launch_bounds__(256)
void k_gemm_h(const __half* __restrict__ Ah1, const __half* __restrict__ Al1,
              const __half* __restrict__ Ah2, const __half* __restrict__ Al2,
              const __half* __restrict__ Wh, const __half* __restrict__ Wl,
              const float* __restrict__ bias, float* __restrict__ C, int M)
{
    extern __shared__ __align__(16) char dsm[];
    float (*stage)[256] = (float(*)[256])(dsm + 2 * STAGE_B);
    uint32_t sbase;
    asm("{ .reg .u64 t; cvta.to.shared.u64 t, %1; cvt.u32.u64 %0, t; }"
        : "=r"(sbase) : "l"(dsm));

    const int tid = threadIdx.x, wid = tid >> 5, lane = tid & 31;
    const int warp_m = wid & 1;
    const int warp_n = wid >> 1;
    const int r0 = blockIdx.x * 128;
    const int K = KPARTS * 128;
    const int NCH = KPARTS * 4;

    const int q0 = tid, q1 = tid + 256;
    const int row0 = q0 >> 2, p0 = q0 & 3;
    const int row1 = q1 >> 2, p1 = q1 & 3;

    auto issue = [&](int c) {
        const __half* Ah = Ah1; const __half* Al = Al1;
        int acol = c * 32;
        if (KPARTS == 2 && c >= 4) { Ah = Ah2; Al = Al2; acol = (c - 4) * 32; }
        uint32_t st = sbase + (c & 1) * STAGE_B;
        int gr0 = r0 + row0, gr1 = r0 + row1;
        cp16(st + row0 * 96 + p0 * 16, Ah + (size_t)gr0 * F + acol + p0 * 8, gr0 < M);
        cp16(st + row1 * 96 + p1 * 16, Ah + (size_t)gr1 * F + acol + p1 * 8, gr1 < M);
        cp16(st + STG_B + row0 * 96 + p0 * 16, Al + (size_t)gr0 * F + acol + p0 * 8, gr0 < M);
        cp16(st + STG_B + row1 * 96 + p1 * 16, Al + (size_t)gr1 * F + acol + p1 * 8, gr1 < M);
        cp16(st + 2 * STG_B + row0 * 96 + p0 * 16, Wh + (size_t)row0 * K + c * 32 + p0 * 8, true);
        cp16(st + 2 * STG_B + row1 * 96 + p1 * 16, Wh + (size_t)row1 * K + c * 32 + p1 * 8, true);
        cp16(st + 3 * STG_B + row0 * 96 + p0 * 16, Wl + (size_t)row0 * K + c * 32 + p0 * 8, true);
        cp16(st + 3 * STG_B + row1 * 96 + p1 * 16, Wl + (size_t)row1 * K + c * 32 + p1 * 8, true);
        CP_COMMIT();
    };

    wmma::fragment<wmma::accumulator, 16, 16, 16, float> acc[4][2];
#pragma unroll
    for (int i = 0; i < 4; i++)
#pragma unroll
        for (int j = 0; j < 2; j++) wmma::fill_fragment(acc[i][j], 0.f);

    issue(0);

    for (int c = 0; c < NCH; ++c) {
        if (c + 1 < NCH) issue(c + 1);
        if (c + 1 < NCH) CP_WAIT1(); else CP_WAIT0();
        __syncthreads();

        const char* st = dsm + (c & 1) * STAGE_B;
        const __half (*sAh)[BKP] = (const __half(*)[BKP])(st);
        const __half (*sAl)[BKP] = (const __half(*)[BKP])(st + STG_B);
        const __half (*sWh)[BKP] = (const __half(*)[BKP])(st + 2 * STG_B);
        const __half (*sWl)[BKP] = (const __half(*)[BKP])(st + 3 * STG_B);

#pragma unroll
        for (int ks = 0; ks < 2; ks++) {
            wmma::fragment<wmma::matrix_b, 16, 16, 16, __half, wmma::col_major> bh[2], bl[2];
#pragma unroll
            for (int wn = 0; wn < 2; wn++) {
                wmma::load_matrix_sync(bh[wn], &sWh[warp_n * 32 + wn * 16][ks * 16], BKP);
                wmma::load_matrix_sync(bl[wn], &sWl[warp_n * 32 + wn * 16][ks * 16], BKP);
            }
#pragma unroll
            for (int wm = 0; wm < 4; wm++) {
                wmma::fragment<wmma::matrix_a, 16, 16, 16, __half, wmma::row_major> ah, al;
                wmma::load_matrix_sync(ah, &sAh[warp_m * 64 + wm * 16][ks * 16], BKP);
                wmma::load_matrix_sync(al, &sAl[warp_m * 64 + wm * 16][ks * 16], BKP);
#pragma unroll
                for (int wn = 0; wn < 2; wn++) {
                    wmma::mma_sync(acc[wm][wn], ah, bh[wn], acc[wm][wn]);
                    wmma::mma_sync(acc[wm][wn], ah, bl[wn], acc[wm][wn]);
                    wmma::mma_sync(acc[wm][wn], al, bh[wn], acc[wm][wn]);
                }
            }
        }
        __syncthreads();
    }

    // epilogue
#pragma unroll
    for (int wm = 0; wm < 4; wm++)
#pragma unroll
        for (int wn = 0; wn < 2; wn++) {
            wmma::store_matrix_sync(stage[wid], acc[wm][wn], 16, wmma::mem_row_major);
            __syncwarp();
            int m0 = warp_m * 64 + wm * 16;
            int n0 = warp_n * 32 + wn * 16;
#pragma unroll
            for (int e = 0; e < 8; e++) {
                int idx = e * 32 + lane;
                int row = idx >> 4, col = idx & 15;
                int gr = r0 + m0 + row;
                if (gr < M) {
                    int gc = n0 + col;
                    float v = stage[wid][idx] + (bias ? bias[gc] : 0.f);
                    C[(size_t)gr * F + gc] = fmaxf(v, 0.f);
                }
            }
            __syncwarp();
        }
}

// ---------------- CSR-bucket build (optional single-level node map) ----------------
template <bool MAPPED>
__global__ void k_bucket(const int* __restrict__ esrc, const int* __restrict__ edst,
                         int E, int M, const int* __restrict__ np)
{
    int t = blockIdx.x * blockDim.x + threadIdx.x;
    int half = E >> 1;
    if (t >= half) return;
#pragma unroll
    for (int q = 0; q < 2; q++) {
        int e = t + q * half;
        int s = esrc[e];
        int d = edst[e];
        if (MAPPED) { s = np[s]; d = np[d]; }
        if (s >= M || d >= M) continue;
        int pos = atomicAdd(&g_deg[d], 1);
        if (pos < CAPD) g_bkt[(size_t)d * CAPD + pos] = s;
    }
}

// ---------------- compose npC = npB o npA ----------------
__global__ void k_collapse(int Msrc)
{
    int v = blockIdx.x * blockDim.x + threadIdx.x;
    if (v <= Msrc) g_npC[v] = g_npB[g_npA[v]];
}

// ---------------- gather-max: warp per dst node; writes hi/lo fp16 splits ----------------
__global__ void k_aggr(const float* __restrict__ y, int M)
{
    int warp = blockIdx.x * (blockDim.x >> 5) + (threadIdx.x >> 5);
    int lane = threadIdx.x & 31;
    if (warp >= M) return;
    int dv = g_deg[warp];
    if (dv > CAPD) dv = CAPD;
    const int* b = g_bkt + (size_t)warp * CAPD;
    float4 acc = ((const float4*)(y + (size_t)warp * F))[lane];
    int i = 0;
    for (; i + 3 < dv; i += 4) {
        int s0 = b[i], s1 = b[i + 1], s2 = b[i + 2], s3 = b[i + 3];
        float4 t0 = ((const float4*)(y + (size_t)s0 * F))[lane];
        float4 t1 = ((const float4*)(y + (size_t)s1 * F))[lane];
        float4 t2 = ((const float4*)(y + (size_t)s2 * F))[lane];
        float4 t3 = ((const float4*)(y + (size_t)s3 * F))[lane];
        acc.x = fmaxf(fmaxf(acc.x, fmaxf(t0.x, t1.x)), fmaxf(t2.x, t3.x));
        acc.y = fmaxf(fmaxf(acc.y, fmaxf(t0.y, t1.y)), fmaxf(t2.y, t3.y));
        acc.z = fmaxf(fmaxf(acc.z, fmaxf(t0.z, t1.z)), fmaxf(t2.z, t3.z));
        acc.w = fmaxf(fmaxf(acc.w, fmaxf(t0.w, t1.w)), fmaxf(t2.w, t3.w));
    }
    for (; i < dv; i++) {
        int s0 = b[i];
        float4 t0 = ((const float4*)(y + (size_t)s0 * F))[lane];
        acc.x = fmaxf(acc.x, t0.x);
        acc.y = fmaxf(acc.y, t0.y);
        acc.z = fmaxf(acc.z, t0.z);
        acc.w = fmaxf(acc.w, t0.w);
    }
    __half h0, h1, h2, h3, l0, l1, l2, l3;
    split2(acc.x, h0, l0); split2(acc.y, h1, l1);
    split2(acc.z, h2, l2); split2(acc.w, h3, l3);
    __half2* oh = (__half2*)(g_ah + (size_t)warp * F + lane * 4);
    __half2* ol = (__half2*)(g_al + (size_t)warp * F + lane * 4);
    oh[0] = __halves2half2(h0, h1); oh[1] = __halves2half2(h2, h3);
    ol[0] = __halves2half2(l0, l1); ol[1] = __halves2half2(l2, l3);
}

// ---------------- scores (wnorm fused) ----------------
__global__ void k_scores(const float* __restrict__ h, const float* __restrict__ w, int M)
{
    __shared__ float s_inv;
    int lane = threadIdx.x & 31;
    if (threadIdx.x < 32) {
        float4 b0 = ((const float4*)w)[lane];
        float sq = b0.x * b0.x + b0.y * b0.y + b0.z * b0.z + b0.w * b0.w;
        for (int o = 16; o > 0; o >>= 1) sq += __shfl_down_sync(0xffffffffu, sq, o);
        if (lane == 0) s_inv = rsqrtf(sq);
    }
    __syncthreads();
    int warp = blockIdx.x * (blockDim.x >> 5) + (threadIdx.x >> 5);
    if (warp >= M) return;
    float4 a = ((const float4*)(h + (size_t)warp * F))[lane];
    float4 b = ((const float4*)w)[lane];
    float d = a.x * b.x + a.y * b.y + a.z * b.z + a.w * b.w;
    for (int o = 16; o > 0; o >>= 1) d += __shfl_down_sync(0xffffffffu, d, o);
    if (lane == 0) g_s[warp] = d * s_inv;
}

// ---------------- per-graph exact radix select (also zeroes pool counters) ----------------
__global__ __launch_bounds__(1024)
void k_select(int n, int kk)
{
    int g = blockIdx.x;
    const float* sg = g_s + (size_t)g * n;
    __shared__ unsigned hist[256];
    __shared__ unsigned s_prefix, s_mask;
    __shared__ int s_need;
    if (threadIdx.x == 0) { s_prefix = 0; s_mask = 0; s_need = kk; }
    __syncthreads();
    for (int pass = 0; pass < 4; ++pass) {
        int shift = 24 - 8 * pass;
        if (threadIdx.x < 256) hist[threadIdx.x] = 0;
        __syncthreads();
        unsigned pre = s_prefix, msk = s_mask;
        for (int i = threadIdx.x; i < n; i += blockDim.x) {
            unsigned key = ordkey(sg[i]);
            if ((key & msk) == pre) atomicAdd(&hist[(key >> shift) & 255], 1u);
        }
        __syncthreads();
        if (threadIdx.x == 0) {
            int need = s_need;
            unsigned cum = 0;
            for (int b = 255; b >= 0; --b) {
                unsigned h = hist[b];
                if (cum + h >= (unsigned)need) {
                    s_need = need - (int)cum;
                    s_prefix = pre | ((unsigned)b << shift);
                    s_mask = msk | (255u << shift);
                    break;
                }
                cum += h;
            }
        }
        __syncthreads();
    }
    if (threadIdx.x == 0) {
        g_thr[g] = s_prefix; g_needeq[g] = s_need;
        g_cnt[g] = 0; g_eqcnt[g] = 0;
    }
}

// ---------------- compact: writes full node map np (initpool fused) ----------------
__global__ void k_compact(int M, int n, int kk, int Mn, int* __restrict__ np)
{
    int v = blockIdx.x * blockDim.x + threadIdx.x;
    if (v > M) return;
    if (v == M) { np[M] = Mn; return; }
    int g = v / n;
    float sv = g_s[v];
    unsigned key = ordkey(sv);
    unsigned T = g_thr[g];
    bool keep = false;
    if (key > T) keep = true;
    else if (key == T && atomicAdd(&g_eqcnt[g], 1) < g_needeq[g]) keep = true;
    if (!keep) { np[v] = Mn; return; }
    int pos = atomicAdd(&g_cnt[g], 1);
    int j = g * kk + pos;
    np[v] = j;
    g_gidx[j] = v;
    g_tanhv[j] = tanhf(sv);
}

// ---------------- gather + per-block readout partials (no atomics) ----------------
// warp per node, 8 nodes/block; block writes private partial to g_part[blockIdx].
__global__ void k_gather_p(const float* __restrict__ h1)
{
    __shared__ float sm[8][128];
    int w = threadIdx.x >> 5;
    int lane = threadIdx.x & 31;
    int j = blockIdx.x * 8 + w;
    int gi = g_gidx[j];
    float t = g_tanhv[j];
    float4 v = ((const float4*)(h1 + (size_t)gi * F))[lane];
    v.x *= t; v.y *= t; v.z *= t; v.w *= t;
    __half h0, h1h, h2, h3, l0, l1, l2, l3;
    split2(v.x, h0, l0); split2(v.y, h1h, l1);
    split2(v.z, h2, l2); split2(v.w, h3, l3);
    __half2* oh = (__half2*)(g_xh + (size_t)j * F + lane * 4);
    __half2* ol = (__half2*)(g_xl + (size_t)j * F + lane * 4);
    oh[0] = __halves2half2(h0, h1h); oh[1] = __halves2half2(h2, h3);
    ol[0] = __halves2half2(l0, l1);  ol[1] = __halves2half2(l2, l3);
    *(float4*)&sm[w][lane * 4] = v;
    __syncthreads();
    int tid = threadIdx.x;
    float* p = g_part + (size_t)blockIdx.x * 2 * F;
    if (tid < 128) {
        float m = sm[0][tid];
#pragma unroll
        for (int r = 1; r < 8; r++) m = fmaxf(m, sm[r][tid]);
        p[tid] = m;
    } else {
        int f = tid - 128;
        float s = sm[0][f];
#pragma unroll
        for (int r = 1; r < 8; r++) s += sm[r][f];
        p[F + f] = s;
    }
}

// ---------------- readout finalize: reduce per-block partials ----------------
__global__ void k_rfinal(int kk, int store)
{
    int g = blockIdx.x;
    int f = threadIdx.x;  // 256
    int nblk = kk >> 3;
    const float* base = g_part + (size_t)g * nblk * 2 * F + f;
    float r;
    if (f < F) {
        float m = -3.4e38f;
        for (int c = 0; c < nblk; c++) m = fmaxf(m, base[(size_t)c * 2 * F]);
        r = m;
    } else {
        float s = 0.f;
        for (int c = 0; c < nblk; c++) s += base[(size_t)c * 2 * F];
        r = s / (float)kk;
    }
    if (store) g_z[g * 2 * F + f] = r;
    else       g_z[g * 2 * F + f] += r;
}

// ---------------- final MLP + sigmoid ----------------
__global__ void k_mlp(const float* __restrict__ Wl1, const float* __restrict__ bl1,
                      const float* __restrict__ Wl2, const float* __restrict__ bl2,
                      const float* __restrict__ Wl3, const float* __restrict__ bl3,
                      float* __restrict__ out)
{
    __shared__ float sz[BGR][2 * F];
    __shared__ float h1[BGR][F];
    __shared__ float h2[BGR][64];
    int t = threadIdx.x;  // 256
    for (int i = t; i < BGR * 2 * F; i += 256) ((float*)sz)[i] = g_z[i];
    __syncthreads();
    for (int o = t; o < BGR * F; o += 256) {
        int g = o >> 7, r = o & 127;
        float a = bl1[r];
        const float* wr = Wl1 + (size_t)r * 2 * F;
        for (int c = 0; c < 2 * F; c++) a += sz[g][c] * wr[c];
        h1[g][r] = fmaxf(a, 0.f);
    }
    __syncthreads();
    for (int o = t; o < BGR * 64; o += 256) {
        int g = o >> 6, r = o & 63;
        float a = bl2[r];
        const float* wr = Wl2 + (size_t)r * F;
        for (int c = 0; c < F; c++) a += h1[g][c] * wr[c];
        h2[g][r] = fmaxf(a, 0.f);
    }
    __syncthreads();
    if (t < BGR) {
        float a = bl3[0];
        for (int c = 0; c < 64; c++) a += h2[t][c] * Wl3[c];
        out[t] = 1.f / (1.f + expf(-a));
    }
}

// ---------------- orchestration (serial stream) ----------------
extern "C" void kernel_launch(void* const* d_in, const int* in_sizes, int n_in,
                              void* d_out, int out_size)
{
    const float* x = (const float*)d_in[0];
    const int* ei = (const int*)d_in[1];
    const float* Wlin[3] = { (const float*)d_in[2], (const float*)d_in[6], (const float*)d_in[10] };
    const float* blin[3] = { (const float*)d_in[3], (const float*)d_in[7], (const float*)d_in[11] };
    const float* Wupd[3] = { (const float*)d_in[4], (const float*)d_in[8], (const float*)d_in[12] };
    const float* wp[3]   = { (const float*)d_in[5], (const float*)d_in[9], (const float*)d_in[13] };
    const float* Wl1 = (const float*)d_in[14];
    const float* bl1 = (const float*)d_in[15];
    const float* Wl2 = (const float*)d_in[16];
    const float* bl2 = (const float*)d_in[17];
    const float* Wl3 = (const float*)d_in[18];
    const float* bl3 = (const float*)d_in[19];

    float *yb, *h1p;
    __half *xh, *xl, *ah, *al, *w1h, *w1l, *w2h, *w2l;
    int *npA, *npB, *npC;
    cudaGetSymbolAddress((void**)&yb, g_y);
    cudaGetSymbolAddress((void**)&h1p, g_h1);
    cudaGetSymbolAddress((void**)&xh, g_xh);
    cudaGetSymbolAddress((void**)&xl, g_xl);
    cudaGetSymbolAddress((void**)&ah, g_ah);
    cudaGetSymbolAddress((void**)&al, g_al);
    cudaGetSymbolAddress((void**)&w1h, g_w1h);
    cudaGetSymbolAddress((void**)&w1l, g_w1l);
    cudaGetSymbolAddress((void**)&w2h, g_w2h);
    cudaGetSymbolAddress((void**)&w2l, g_w2l);
    cudaGetSymbolAddress((void**)&npA, g_npA);
    cudaGetSymbolAddress((void**)&npB, g_npB);
    cudaGetSymbolAddress((void**)&npC, g_npC);

    static int init_done = 0;
    if (!init_done) {
        cudaFuncSetAttribute(k_gemm_h<1>, cudaFuncAttributeMaxDynamicSharedMemorySize, SMEM_H);
        cudaFuncSetAttribute(k_gemm_h<2>, cudaFuncAttributeMaxDynamicSharedMemorySize, SMEM_H);
        init_done = 1;
    }

    const int Ms[3] = { 100000, 80000, 64000 };
    const int kks[3] = { 10000, 8000, 6400 };

    const int* es = ei;
    const int* ed = ei + EMAX;

    k_split<<<(NMAX * F / 4 + 255) / 256, 256>>>(x, xh, xl, NMAX * F / 4);

    for (int st = 0; st < 3; ++st) {
        int M = Ms[st];
        int gridG = (M + 127) / 128;
        int kk = kks[st], n = M / BGR, Mn = BGR * kk;

        k_prep<<<(M + 255) / 256, 256>>>(Wlin[st], Wupd[st], M);
        if (st == 2)
            k_collapse<<<(NMAX + 1 + 255) / 256, 256>>>(NMAX);

        // SAGEConv
        k_gemm_h<1><<<gridG, 256, SMEM_H>>>(xh, xl, nullptr, nullptr, w1h, w1l, blin[st], yb, M);
        if (st == 0)
            k_bucket<false><<<(EMAX / 2 + 255) / 256, 256>>>(es, ed, EMAX, M, nullptr);
        else if (st == 1)
            k_bucket<true><<<(EMAX / 2 + 255) / 256, 256>>>(es, ed, EMAX, M, npA);
        else
            k_bucket<true><<<(EMAX / 2 + 255) / 256, 256>>>(es, ed, EMAX, M, npC);
        k_aggr<<<(M + 7) / 8, 256>>>(yb, M);
        k_gemm_h<2><<<gridG, 256, SMEM_H>>>(ah, al, xh, xl, w2h, w2l, nullptr, h1p, M);

        // TopK pool
        k_scores<<<(M + 3) / 4, 128>>>(h1p, wp[st], M);
        k_select<<<BGR, 1024>>>(n, kk);
        int* npOut = (st == 0) ? npA : npB;
        k_compact<<<(M + 1 + 255) / 256, 256>>>(M, n, kk, Mn, npOut);
        k_gather_p<<<Mn / 8, 256>>>(h1p);

        // readout finalize
        k_rfinal<<<BGR, 256>>>(kk, st == 0 ? 1 : 0);
    }

    k_mlp<<<1, 256>>>(Wl1, bl1, Wl2, bl2, Wl3, bl3, (float*)d_out);
}

// round 15
// speedup vs baseline: 1.0257x; 1.0257x over previous
#include <cuda_runtime.h>
#include <cuda_fp16.h>
#include <math.h>
#include <stdint.h>
#include <mma.h>

using namespace nvcuda;

#define F 128
#define NMAX 100000
#define EMAX 1600000
#define BGR 8
#define CH 40
#define CAPD 96
#define BKP 48

// ---------------- device scratch ----------------
__device__ float  g_y[NMAX * F];
__device__ float  g_h1[NMAX * F];
__device__ float  g_h2[80000 * F];
__device__ __half g_xh[NMAX * F];
__device__ __half g_xl[NMAX * F];
__device__ __half g_ah[NMAX * F];
__device__ __half g_al[NMAX * F];
__device__ __half g_w1h[128 * 128];
__device__ __half g_w1l[128 * 128];
__device__ __half g_w2h[128 * 256];
__device__ __half g_w2l[128 * 256];
__device__ int    g_npA[NMAX + 1];
__device__ int    g_npB[80001];
__device__ int    g_npC[NMAX + 1];
__device__ int    g_deg[NMAX];
__device__ int    g_bkt[NMAX * CAPD];
__device__ float  g_s[NMAX];
__device__ int    g_gidx[80000];
__device__ float  g_tanhv[80000];
__device__ unsigned g_thr[BGR];
__device__ int    g_needeq[BGR];
__device__ int    g_cnt[BGR];
__device__ int    g_eqcnt[BGR];
__device__ float  g_z[BGR * 2 * F];
__device__ float  g_part[BGR * CH * 2 * F];

__device__ __forceinline__ unsigned ordkey(float f) {
    unsigned u = __float_as_uint(f);
    return (u & 0x80000000u) ? ~u : (u | 0x80000000u);
}

__device__ __forceinline__ void split2(float v, __half& h, __half& l) {
    h = __float2half_rn(v);
    l = __float2half_rn(v - __half2float(h));
}

__device__ __forceinline__ void cp16(uint32_t saddr, const void* gptr, bool valid) {
    int sz = valid ? 16 : 0;
    asm volatile("cp.async.cg.shared.global [%0], [%1], 16, %2;"
                 :: "r"(saddr), "l"(gptr), "r"(sz));
}
#define CP_COMMIT() asm volatile("cp.async.commit_group;" ::: "memory")
#define CP_WAIT1()  asm volatile("cp.async.wait_group 1;" ::: "memory")
#define CP_WAIT0()  asm volatile("cp.async.wait_group 0;" ::: "memory")

// ---------------- stage-0 input split ----------------
__global__ void k_split(const float* __restrict__ src, __half* __restrict__ hi,
                        __half* __restrict__ lo, int n4)
{
    int i = blockIdx.x * blockDim.x + threadIdx.x;
    if (i >= n4) return;
    float4 v = ((const float4*)src)[i];
    __half h0, h1, h2, h3, l0, l1, l2, l3;
    split2(v.x, h0, l0); split2(v.y, h1, l1);
    split2(v.z, h2, l2); split2(v.w, h3, l3);
    ((__half2*)hi)[i * 2 + 0] = __halves2half2(h0, h1);
    ((__half2*)hi)[i * 2 + 1] = __halves2half2(h2, h3);
    ((__half2*)lo)[i * 2 + 0] = __halves2half2(l0, l1);
    ((__half2*)lo)[i * 2 + 1] = __halves2half2(l2, l3);
}

// ---------------- per-stage prep: deg zero + weight splits ----------------
__global__ void k_prep(const float* __restrict__ W1, const float* __restrict__ W2, int M)
{
    int i = blockIdx.x * blockDim.x + threadIdx.x;
    if (i < M) g_deg[i] = 0;
    const int n1 = 128 * 128 / 4;
    const int n2 = 128 * 256 / 4;
    if (i < n1) {
        float4 v = ((const float4*)W1)[i];
        __half h0, h1, h2, h3, l0, l1, l2, l3;
        split2(v.x, h0, l0); split2(v.y, h1, l1);
        split2(v.z, h2, l2); split2(v.w, h3, l3);
        ((__half2*)g_w1h)[i * 2 + 0] = __halves2half2(h0, h1);
        ((__half2*)g_w1h)[i * 2 + 1] = __halves2half2(h2, h3);
        ((__half2*)g_w1l)[i * 2 + 0] = __halves2half2(l0, l1);
        ((__half2*)g_w1l)[i * 2 + 1] = __halves2half2(l2, l3);
    } else if (i < n1 + n2) {
        int idx = i - n1;
        float4 v = ((const float4*)W2)[idx];
        __half h0, h1, h2, h3, l0, l1, l2, l3;
        split2(v.x, h0, l0); split2(v.y, h1, l1);
        split2(v.z, h2, l2); split2(v.w, h3, l3);
        ((__half2*)g_w2h)[idx * 2 + 0] = __halves2half2(h0, h1);
        ((__half2*)g_w2h)[idx * 2 + 1] = __halves2half2(h2, h3);
        ((__half2*)g_w2l)[idx * 2 + 0] = __halves2half2(l0, l1);
        ((__half2*)g_w2l)[idx * 2 + 1] = __halves2half2(l2, l3);
    }
}

// ---------------- fp16-split wmma GEMM with cp.async double buffering ----------------
// If wp != nullptr, also computes g_s[row] = relu_out_row . wp / ||wp|| (no atomics).
#define STG_B 12288
#define STAGE_B (4 * STG_B)
#define SMEM_H (2 * STAGE_B + 8192 + 2560 + 512 + 16)

template <int KPARTS>
__global__ __launch_bounds__(256)
void k_gemm_h(const __half* __restrict__ Ah1, const __half* __restrict__ Al1,
              const __half* __restrict__ Ah2, const __half* __restrict__ Al2,
              const __half* __restrict__ Wh, const __half* __restrict__ Wl,
              const float* __restrict__ bias, const float* __restrict__ wp,
              float* __restrict__ C, int M)
{
    extern __shared__ __align__(16) char dsm[];
    float (*stage)[256] = (float(*)[256])(dsm + 2 * STAGE_B);
    float (*srow)[5] = (float(*)[5])(dsm + 2 * STAGE_B + 8192);       // 128 x 5 (pad)
    float* swp  = (float*)(dsm + 2 * STAGE_B + 8192 + 2560);          // 128
    float* sinv = (float*)(dsm + 2 * STAGE_B + 8192 + 2560 + 512);
    uint32_t sbase;
    asm("{ .reg .u64 t; cvta.to.shared.u64 t, %1; cvt.u32.u64 %0, t; }"
        : "=r"(sbase) : "l"(dsm));

    const int tid = threadIdx.x, wid = tid >> 5, lane = tid & 31;
    const int warp_m = wid & 1;
    const int warp_n = wid >> 1;
    const int r0 = blockIdx.x * 128;
    const int K = KPARTS * 128;
    const int NCH = KPARTS * 4;

    if (wp && tid < 128) {
        swp[tid] = wp[tid];
        srow[tid][0] = 0.f; srow[tid][1] = 0.f;
        srow[tid][2] = 0.f; srow[tid][3] = 0.f;
    }

    const int q0 = tid, q1 = tid + 256;
    const int row0 = q0 >> 2, p0 = q0 & 3;
    const int row1 = q1 >> 2, p1 = q1 & 3;

    auto issue = [&](int c) {
        const __half* Ah = Ah1; const __half* Al = Al1;
        int acol = c * 32;
        if (KPARTS == 2 && c >= 4) { Ah = Ah2; Al = Al2; acol = (c - 4) * 32; }
        uint32_t st = sbase + (c & 1) * STAGE_B;
        int gr0 = r0 + row0, gr1 = r0 + row1;
        cp16(st + row0 * 96 + p0 * 16, Ah + (size_t)gr0 * F + acol + p0 * 8, gr0 < M);
        cp16(st + row1 * 96 + p1 * 16, Ah + (size_t)gr1 * F + acol + p1 * 8, gr1 < M);
        cp16(st + STG_B + row0 * 96 + p0 * 16, Al + (size_t)gr0 * F + acol + p0 * 8, gr0 < M);
        cp16(st + STG_B + row1 * 96 + p1 * 16, Al + (size_t)gr1 * F + acol + p1 * 8, gr1 < M);
        cp16(st + 2 * STG_B + row0 * 96 + p0 * 16, Wh + (size_t)row0 * K + c * 32 + p0 * 8, true);
        cp16(st + 2 * STG_B + row1 * 96 + p1 * 16, Wh + (size_t)row1 * K + c * 32 + p1 * 8, true);
        cp16(st + 3 * STG_B + row0 * 96 + p0 * 16, Wl + (size_t)row0 * K + c * 32 + p0 * 8, true);
        cp16(st + 3 * STG_B + row1 * 96 + p1 * 16, Wl + (size_t)row1 * K + c * 32 + p1 * 8, true);
        CP_COMMIT();
    };

    wmma::fragment<wmma::accumulator, 16, 16, 16, float> acc[4][2];
#pragma unroll
    for (int i = 0; i < 4; i++)
#pragma unroll
        for (int j = 0; j < 2; j++) wmma::fill_fragment(acc[i][j], 0.f);

    issue(0);

    for (int c = 0; c < NCH; ++c) {
        if (c + 1 < NCH) issue(c + 1);
        if (c + 1 < NCH) CP_WAIT1(); else CP_WAIT0();
        __syncthreads();

        const char* st = dsm + (c & 1) * STAGE_B;
        const __half (*sAh)[BKP] = (const __half(*)[BKP])(st);
        const __half (*sAl)[BKP] = (const __half(*)[BKP])(st + STG_B);
        const __half (*sWh)[BKP] = (const __half(*)[BKP])(st + 2 * STG_B);
        const __half (*sWl)[BKP] = (const __half(*)[BKP])(st + 3 * STG_B);

#pragma unroll
        for (int ks = 0; ks < 2; ks++) {
            wmma::fragment<wmma::matrix_b, 16, 16, 16, __half, wmma::col_major> bh[2], bl[2];
#pragma unroll
            for (int wn = 0; wn < 2; wn++) {
                wmma::load_matrix_sync(bh[wn], &sWh[warp_n * 32 + wn * 16][ks * 16], BKP);
                wmma::load_matrix_sync(bl[wn], &sWl[warp_n * 32 + wn * 16][ks * 16], BKP);
            }
#pragma unroll
            for (int wm = 0; wm < 4; wm++) {
                wmma::fragment<wmma::matrix_a, 16, 16, 16, __half, wmma::row_major> ah, al;
                wmma::load_matrix_sync(ah, &sAh[warp_m * 64 + wm * 16][ks * 16], BKP);
                wmma::load_matrix_sync(al, &sAl[warp_m * 64 + wm * 16][ks * 16], BKP);
#pragma unroll
                for (int wn = 0; wn < 2; wn++) {
                    wmma::mma_sync(acc[wm][wn], ah, bh[wn], acc[wm][wn]);
                    wmma::mma_sync(acc[wm][wn], ah, bl[wn], acc[wm][wn]);
                    wmma::mma_sync(acc[wm][wn], al, bh[wn], acc[wm][wn]);
                }
            }
        }
        __syncthreads();
    }

    // epilogue (+ optional atomic-free fused score partials)
#pragma unroll
    for (int wm = 0; wm < 4; wm++)
#pragma unroll
        for (int wn = 0; wn < 2; wn++) {
            wmma::store_matrix_sync(stage[wid], acc[wm][wn], 16, wmma::mem_row_major);
            __syncwarp();
            int m0 = warp_m * 64 + wm * 16;
            int n0 = warp_n * 32 + wn * 16;
#pragma unroll
            for (int e = 0; e < 8; e++) {
                int idx = e * 32 + lane;
                int row = idx >> 4, col = idx & 15;
                int gr = r0 + m0 + row;
                int gc = n0 + col;
                float v = 0.f;
                if (gr < M) {
                    v = stage[wid][idx] + (bias ? bias[gc] : 0.f);
                    v = fmaxf(v, 0.f);
                    C[(size_t)gr * F + gc] = v;
                }
                if (wp) {
                    float p = v * swp[gc];
                    // reduce across the 16 lanes sharing this row (half-warp butterfly)
#pragma unroll
                    for (int o = 1; o < 16; o <<= 1)
                        p += __shfl_xor_sync(0xffffffffu, p, o);
                    if ((lane & 15) == 0)
                        srow[m0 + row][warp_n] += p;   // slot owned by this warp only
                }
            }
            __syncwarp();
        }

    if (wp) {
        __syncthreads();
        if (tid < 32) {
            float sq = 0.f;
            for (int i = tid; i < 128; i += 32) { float w = swp[i]; sq += w * w; }
            for (int o = 16; o > 0; o >>= 1) sq += __shfl_down_sync(0xffffffffu, sq, o);
            if (tid == 0) *sinv = rsqrtf(sq);
        }
        __syncthreads();
        if (tid < 128) {
            int gr = r0 + tid;
            if (gr < M)
                g_s[gr] = (srow[tid][0] + srow[tid][1] + srow[tid][2] + srow[tid][3]) * (*sinv);
        }
    }
}

// ---------------- CSR-bucket build (optional single-level node map) ----------------
template <bool MAPPED>
__global__ void k_bucket(const int* __restrict__ esrc, const int* __restrict__ edst,
                         int E, int M, const int* __restrict__ np)
{
    int t = blockIdx.x * blockDim.x + threadIdx.x;
    int half = E >> 1;
    if (t >= half) return;
#pragma unroll
    for (int q = 0; q < 2; q++) {
        int e = t + q * half;
        int s = esrc[e];
        int d = edst[e];
        if (MAPPED) { s = np[s]; d = np[d]; }
        if (s >= M || d >= M) continue;
        int pos = atomicAdd(&g_deg[d], 1);
        if (pos < CAPD) g_bkt[(size_t)d * CAPD + pos] = s;
    }
}

// ---------------- compose npC = npB o npA ----------------
__global__ void k_collapse(int Msrc)
{
    int v = blockIdx.x * blockDim.x + threadIdx.x;
    if (v <= Msrc) g_npC[v] = g_npB[g_npA[v]];
}

// ---------------- gather-max: warp per dst node; writes hi/lo fp16 splits ----------------
__global__ void k_aggr(const float* __restrict__ y, int M)
{
    int warp = blockIdx.x * (blockDim.x >> 5) + (threadIdx.x >> 5);
    int lane = threadIdx.x & 31;
    if (warp >= M) return;
    int dv = g_deg[warp];
    if (dv > CAPD) dv = CAPD;
    const int* b = g_bkt + (size_t)warp * CAPD;
    float4 acc = ((const float4*)(y + (size_t)warp * F))[lane];
    int i = 0;
    for (; i + 3 < dv; i += 4) {
        int s0 = b[i], s1 = b[i + 1], s2 = b[i + 2], s3 = b[i + 3];
        float4 t0 = ((const float4*)(y + (size_t)s0 * F))[lane];
        float4 t1 = ((const float4*)(y + (size_t)s1 * F))[lane];
        float4 t2 = ((const float4*)(y + (size_t)s2 * F))[lane];
        float4 t3 = ((const float4*)(y + (size_t)s3 * F))[lane];
        acc.x = fmaxf(fmaxf(acc.x, fmaxf(t0.x, t1.x)), fmaxf(t2.x, t3.x));
        acc.y = fmaxf(fmaxf(acc.y, fmaxf(t0.y, t1.y)), fmaxf(t2.y, t3.y));
        acc.z = fmaxf(fmaxf(acc.z, fmaxf(t0.z, t1.z)), fmaxf(t2.z, t3.z));
        acc.w = fmaxf(fmaxf(acc.w, fmaxf(t0.w, t1.w)), fmaxf(t2.w, t3.w));
    }
    for (; i < dv; i++) {
        int s0 = b[i];
        float4 t0 = ((const float4*)(y + (size_t)s0 * F))[lane];
        acc.x = fmaxf(acc.x, t0.x);
        acc.y = fmaxf(acc.y, t0.y);
        acc.z = fmaxf(acc.z, t0.z);
        acc.w = fmaxf(acc.w, t0.w);
    }
    __half h0, h1, h2, h3, l0, l1, l2, l3;
    split2(acc.x, h0, l0); split2(acc.y, h1, l1);
    split2(acc.z, h2, l2); split2(acc.w, h3, l3);
    __half2* oh = (__half2*)(g_ah + (size_t)warp * F + lane * 4);
    __half2* ol = (__half2*)(g_al + (size_t)warp * F + lane * 4);
    oh[0] = __halves2half2(h0, h1); oh[1] = __halves2half2(h2, h3);
    ol[0] = __halves2half2(l0, l1); ol[1] = __halves2half2(l2, l3);
}

// ---------------- per-graph exact radix select (also zeroes pool counters) ----------------
__global__ __launch_bounds__(1024)
void k_select(int n, int kk)
{
    int g = blockIdx.x;
    const float* sg = g_s + (size_t)g * n;
    __shared__ unsigned hist[256];
    __shared__ unsigned s_prefix, s_mask;
    __shared__ int s_need;
    if (threadIdx.x == 0) { s_prefix = 0; s_mask = 0; s_need = kk; }
    __syncthreads();
    for (int pass = 0; pass < 4; ++pass) {
        int shift = 24 - 8 * pass;
        if (threadIdx.x < 256) hist[threadIdx.x] = 0;
        __syncthreads();
        unsigned pre = s_prefix, msk = s_mask;
        for (int i = threadIdx.x; i < n; i += blockDim.x) {
            unsigned key = ordkey(sg[i]);
            if ((key & msk) == pre) atomicAdd(&hist[(key >> shift) & 255], 1u);
        }
        __syncthreads();
        if (threadIdx.x == 0) {
            int need = s_need;
            unsigned cum = 0;
            for (int b = 255; b >= 0; --b) {
                unsigned h = hist[b];
                if (cum + h >= (unsigned)need) {
                    s_need = need - (int)cum;
                    s_prefix = pre | ((unsigned)b << shift);
                    s_mask = msk | (255u << shift);
                    break;
                }
                cum += h;
            }
        }
        __syncthreads();
    }
    if (threadIdx.x == 0) {
        g_thr[g] = s_prefix; g_needeq[g] = s_need;
        g_cnt[g] = 0; g_eqcnt[g] = 0;
    }
}

// ---------------- compact: writes full node map np (initpool fused) ----------------
__global__ void k_compact(int M, int n, int kk, int Mn, int* __restrict__ np)
{
    int v = blockIdx.x * blockDim.x + threadIdx.x;
    if (v > M) return;
    if (v == M) { np[M] = Mn; return; }
    int g = v / n;
    float sv = g_s[v];
    unsigned key = ordkey(sv);
    unsigned T = g_thr[g];
    bool keep = false;
    if (key > T) keep = true;
    else if (key == T && atomicAdd(&g_eqcnt[g], 1) < g_needeq[g]) keep = true;
    if (!keep) { np[v] = Mn; return; }
    int pos = atomicAdd(&g_cnt[g], 1);
    int j = g * kk + pos;
    np[v] = j;
    g_gidx[j] = v;
    g_tanhv[j] = tanhf(sv);
}

// ---------------- gather: float out + fp16 splits for next gemm1 ----------------
__global__ void k_gather(const float* __restrict__ h, float* __restrict__ xnew, int Mn)
{
    int idx = blockIdx.x * blockDim.x + threadIdx.x;
    int j = idx >> 5, q = idx & 31;
    if (j >= Mn) return;
    float t = g_tanhv[j];
    float4 v = *(const float4*)(h + (size_t)g_gidx[j] * F + q * 4);
    v.x *= t; v.y *= t; v.z *= t; v.w *= t;
    *(float4*)(xnew + (size_t)j * F + q * 4) = v;
    __half h0, h1, h2, h3, l0, l1, l2, l3;
    split2(v.x, h0, l0); split2(v.y, h1, l1);
    split2(v.z, h2, l2); split2(v.w, h3, l3);
    __half2* oh = (__half2*)(g_xh + (size_t)j * F + q * 4);
    __half2* ol = (__half2*)(g_xl + (size_t)j * F + q * 4);
    oh[0] = __halves2half2(h0, h1); oh[1] = __halves2half2(h2, h3);
    ol[0] = __halves2half2(l0, l1); ol[1] = __halves2half2(l2, l3);
}

// ---------------- readout ----------------
__global__ void k_rpart(const float* __restrict__ x, int kk)
{
    int g = blockIdx.x / CH, c = blockIdx.x % CH;
    int rpc = kk / CH;
    int f = threadIdx.x;  // 128
    const float* base = x + ((size_t)g * kk + (size_t)c * rpc) * F + f;
    float vmax = -3.4e38f, vsum = 0.f;
    for (int r = 0; r < rpc; r++) {
        float v = base[(size_t)r * F];
        vmax = fmaxf(vmax, v);
        vsum += v;
    }
    float* p = g_part + (size_t)blockIdx.x * 2 * F;
    p[f] = vmax;
    p[F + f] = vsum;
}

__global__ void k_rfinal(int kk, int store)
{
    int g = blockIdx.x;
    int f = threadIdx.x;  // 256
    const float* p = g_part + (size_t)g * CH * 2 * F;
    float r;
    if (f < F) {
        float m = -3.4e38f;
        for (int c = 0; c < CH; c++) m = fmaxf(m, p[c * 2 * F + f]);
        r = m;
    } else {
        float s = 0.f;
        for (int c = 0; c < CH; c++) s += p[c * 2 * F + f];
        r = s / (float)kk;
    }
    if (store) g_z[g * 2 * F + f] = r;
    else       g_z[g * 2 * F + f] += r;
}

// ---------------- final MLP + sigmoid ----------------
__global__ void k_mlp(const float* __restrict__ Wl1, const float* __restrict__ bl1,
                      const float* __restrict__ Wl2, const float* __restrict__ bl2,
                      const float* __restrict__ Wl3, const float* __restrict__ bl3,
                      float* __restrict__ out)
{
    __shared__ float sz[BGR][2 * F];
    __shared__ float h1[BGR][F];
    __shared__ float h2[BGR][64];
    int t = threadIdx.x;  // 256
    for (int i = t; i < BGR * 2 * F; i += 256) ((float*)sz)[i] = g_z[i];
    __syncthreads();
    for (int o = t; o < BGR * F; o += 256) {
        int g = o >> 7, r = o & 127;
        float a = bl1[r];
        const float* wr = Wl1 + (size_t)r * 2 * F;
        for (int c = 0; c < 2 * F; c++) a += sz[g][c] * wr[c];
        h1[g][r] = fmaxf(a, 0.f);
    }
    __syncthreads();
    for (int o = t; o < BGR * 64; o += 256) {
        int g = o >> 6, r = o & 63;
        float a = bl2[r];
        const float* wr = Wl2 + (size_t)r * F;
        for (int c = 0; c < F; c++) a += h1[g][c] * wr[c];
        h2[g][r] = fmaxf(a, 0.f);
    }
    __syncthreads();
    if (t < BGR) {
        float a = bl3[0];
        for (int c = 0; c < 64; c++) a += h2[t][c] * Wl3[c];
        out[t] = 1.f / (1.f + expf(-a));
    }
}

// ---------------- orchestration (serial stream) ----------------
extern "C" void kernel_launch(void* const* d_in, const int* in_sizes, int n_in,
                              void* d_out, int out_size)
{
    const float* x = (const float*)d_in[0];
    const int* ei = (const int*)d_in[1];
    const float* Wlin[3] = { (const float*)d_in[2], (const float*)d_in[6], (const float*)d_in[10] };
    const float* blin[3] = { (const float*)d_in[3], (const float*)d_in[7], (const float*)d_in[11] };
    const float* Wupd[3] = { (const float*)d_in[4], (const float*)d_in[8], (const float*)d_in[12] };
    const float* wp[3]   = { (const float*)d_in[5], (const float*)d_in[9], (const float*)d_in[13] };
    const float* Wl1 = (const float*)d_in[14];
    const float* bl1 = (const float*)d_in[15];
    const float* Wl2 = (const float*)d_in[16];
    const float* bl2 = (const float*)d_in[17];
    const float* Wl3 = (const float*)d_in[18];
    const float* bl3 = (const float*)d_in[19];

    float *yb, *h1p, *h2p;
    __half *xh, *xl, *ah, *al, *w1h, *w1l, *w2h, *w2l;
    int *npA, *npB, *npC;
    cudaGetSymbolAddress((void**)&yb, g_y);
    cudaGetSymbolAddress((void**)&h1p, g_h1);
    cudaGetSymbolAddress((void**)&h2p, g_h2);
    cudaGetSymbolAddress((void**)&xh, g_xh);
    cudaGetSymbolAddress((void**)&xl, g_xl);
    cudaGetSymbolAddress((void**)&ah, g_ah);
    cudaGetSymbolAddress((void**)&al, g_al);
    cudaGetSymbolAddress((void**)&w1h, g_w1h);
    cudaGetSymbolAddress((void**)&w1l, g_w1l);
    cudaGetSymbolAddress((void**)&w2h, g_w2h);
    cudaGetSymbolAddress((void**)&w2l, g_w2l);
    cudaGetSymbolAddress((void**)&npA, g_npA);
    cudaGetSymbolAddress((void**)&npB, g_npB);
    cudaGetSymbolAddress((void**)&npC, g_npC);

    static int init_done = 0;
    if (!init_done) {
        cudaFuncSetAttribute(k_gemm_h<1>, cudaFuncAttributeMaxDynamicSharedMemorySize, SMEM_H);
        cudaFuncSetAttribute(k_gemm_h<2>, cudaFuncAttributeMaxDynamicSharedMemorySize, SMEM_H);
        init_done = 1;
    }

    const int Ms[3] = { 100000, 80000, 64000 };
    const int kks[3] = { 10000, 8000, 6400 };

    const int* es = ei;
    const int* ed = ei + EMAX;

    k_split<<<(NMAX * F / 4 + 255) / 256, 256>>>(x, xh, xl, NMAX * F / 4);

    for (int st = 0; st < 3; ++st) {
        int M = Ms[st];
        int gridG = (M + 127) / 128;
        int kk = kks[st], n = M / BGR, Mn = BGR * kk;

        k_prep<<<(M + 255) / 256, 256>>>(Wlin[st], Wupd[st], M);
        if (st == 2)
            k_collapse<<<(NMAX + 1 + 255) / 256, 256>>>(NMAX);

        // SAGEConv
        k_gemm_h<1><<<gridG, 256, SMEM_H>>>(xh, xl, nullptr, nullptr, w1h, w1l,
                                            blin[st], nullptr, yb, M);
        if (st == 0)
            k_bucket<false><<<(EMAX / 2 + 255) / 256, 256>>>(es, ed, EMAX, M, nullptr);
        else if (st == 1)
            k_bucket<true><<<(EMAX / 2 + 255) / 256, 256>>>(es, ed, EMAX, M, npA);
        else
            k_bucket<true><<<(EMAX / 2 + 255) / 256, 256>>>(es, ed, EMAX, M, npC);
        k_aggr<<<(M + 7) / 8, 256>>>(yb, M);
        k_gemm_h<2><<<gridG, 256, SMEM_H>>>(ah, al, xh, xl, w2h, w2l,
                                            nullptr, wp[st], h1p, M);

        // TopK pool (scores already computed by gemm2 epilogue)
        k_select<<<BGR, 1024>>>(n, kk);
        int* npOut = (st == 0) ? npA : npB;
        k_compact<<<(M + 1 + 255) / 256, 256>>>(M, n, kk, Mn, npOut);
        k_gather<<<(Mn * 32 + 255) / 256, 256>>>(h1p, h2p, Mn);

        // readout
        k_rpart<<<BGR * CH, 128>>>(h2p, kk);
        k_rfinal<<<BGR, 256>>>(kk, st == 0 ? 1 : 0);
    }

    k_mlp<<<1, 256>>>(Wl1, bl1, Wl2, bl2, Wl3, bl3, (float*)d_out);
}

// round 16
// speedup vs baseline: 1.0276x; 1.0019x over previous
#include <cuda_runtime.h>
#include <cuda_fp16.h>
#include <math.h>
#include <stdint.h>
#include <mma.h>

using namespace nvcuda;

#define F 128
#define NMAX 100000
#define EMAX 1600000
#define BGR 8
#define CH 40
#define CAPD 96
#define BKP 48

// ---------------- device scratch ----------------
__device__ float  g_y[NMAX * F];
__device__ float  g_h1[NMAX * F];
__device__ float  g_h2[80000 * F];
__device__ __half g_xh[NMAX * F];
__device__ __half g_xl[NMAX * F];
__device__ __half g_ah[NMAX * F];
__device__ __half g_al[NMAX * F];
__device__ __half g_w1h[128 * 128];
__device__ __half g_w1l[128 * 128];
__device__ __half g_w2h[128 * 256];
__device__ __half g_w2l[128 * 256];
__device__ int    g_npA[NMAX + 1];
__device__ int    g_npB[80001];
__device__ int    g_npC[NMAX + 1];
__device__ int    g_deg[NMAX];
__device__ int    g_bkt[NMAX * CAPD];
__device__ float  g_s[NMAX];
__device__ int    g_gidx[80000];
__device__ float  g_tanhv[80000];
__device__ unsigned g_thr[BGR];
__device__ int    g_needeq[BGR];
__device__ int    g_cnt[BGR];
__device__ int    g_eqcnt[BGR];
__device__ float  g_z[BGR * 2 * F];
__device__ float  g_part[BGR * CH * 2 * F];

__device__ __forceinline__ unsigned ordkey(float f) {
    unsigned u = __float_as_uint(f);
    return (u & 0x80000000u) ? ~u : (u | 0x80000000u);
}

__device__ __forceinline__ void split2(float v, __half& h, __half& l) {
    h = __float2half_rn(v);
    l = __float2half_rn(v - __half2float(h));
}

__device__ __forceinline__ void cp16(uint32_t saddr, const void* gptr, bool valid) {
    int sz = valid ? 16 : 0;
    asm volatile("cp.async.cg.shared.global [%0], [%1], 16, %2;"
                 :: "r"(saddr), "l"(gptr), "r"(sz));
}
#define CP_COMMIT() asm volatile("cp.async.commit_group;" ::: "memory")
#define CP_WAIT1()  asm volatile("cp.async.wait_group 1;" ::: "memory")
#define CP_WAIT0()  asm volatile("cp.async.wait_group 0;" ::: "memory")

// ---------------- stage-0 input split ----------------
__global__ void k_split(const float* __restrict__ src, __half* __restrict__ hi,
                        __half* __restrict__ lo, int n4)
{
    int i = blockIdx.x * blockDim.x + threadIdx.x;
    if (i >= n4) return;
    float4 v = ((const float4*)src)[i];
    __half h0, h1, h2, h3, l0, l1, l2, l3;
    split2(v.x, h0, l0); split2(v.y, h1, l1);
    split2(v.z, h2, l2); split2(v.w, h3, l3);
    ((__half2*)hi)[i * 2 + 0] = __halves2half2(h0, h1);
    ((__half2*)hi)[i * 2 + 1] = __halves2half2(h2, h3);
    ((__half2*)lo)[i * 2 + 0] = __halves2half2(l0, l1);
    ((__half2*)lo)[i * 2 + 1] = __halves2half2(l2, l3);
}

// ---------------- weight splits (main stream; gemm1 depends on it) ----------------
__global__ void k_prepw(const float* __restrict__ W1, const float* __restrict__ W2)
{
    int i = blockIdx.x * blockDim.x + threadIdx.x;
    const int n1 = 128 * 128 / 4;
    const int n2 = 128 * 256 / 4;
    if (i < n1) {
        float4 v = ((const float4*)W1)[i];
        __half h0, h1, h2, h3, l0, l1, l2, l3;
        split2(v.x, h0, l0); split2(v.y, h1, l1);
        split2(v.z, h2, l2); split2(v.w, h3, l3);
        ((__half2*)g_w1h)[i * 2 + 0] = __halves2half2(h0, h1);
        ((__half2*)g_w1h)[i * 2 + 1] = __halves2half2(h2, h3);
        ((__half2*)g_w1l)[i * 2 + 0] = __halves2half2(l0, l1);
        ((__half2*)g_w1l)[i * 2 + 1] = __halves2half2(l2, l3);
    } else if (i < n1 + n2) {
        int idx = i - n1;
        float4 v = ((const float4*)W2)[idx];
        __half h0, h1, h2, h3, l0, l1, l2, l3;
        split2(v.x, h0, l0); split2(v.y, h1, l1);
        split2(v.z, h2, l2); split2(v.w, h3, l3);
        ((__half2*)g_w2h)[idx * 2 + 0] = __halves2half2(h0, h1);
        ((__half2*)g_w2h)[idx * 2 + 1] = __halves2half2(h2, h3);
        ((__half2*)g_w2l)[idx * 2 + 0] = __halves2half2(l0, l1);
        ((__half2*)g_w2l)[idx * 2 + 1] = __halves2half2(l2, l3);
    }
}

__global__ void k_zerodeg(int M)
{
    int i = blockIdx.x * blockDim.x + threadIdx.x;
    if (i < M) g_deg[i] = 0;
}

// ---------------- fp16-split wmma GEMM with cp.async double buffering ----------------
#define STG_B 12288
#define STAGE_B (4 * STG_B)
#define SMEM_H (2 * STAGE_B + 8192)

template <int KPARTS>
__global__ __launch_bounds__(256)
void k_gemm_h(const __half* __restrict__ Ah1, const __half* __restrict__ Al1,
              const __half* __restrict__ Ah2, const __half* __restrict__ Al2,
              const __half* __restrict__ Wh, const __half* __restrict__ Wl,
              const float* __restrict__ bias, float* __restrict__ C, int M)
{
    extern __shared__ __align__(16) char dsm[];
    float (*stage)[256] = (float(*)[256])(dsm + 2 * STAGE_B);
    uint32_t sbase;
    asm("{ .reg .u64 t; cvta.to.shared.u64 t, %1; cvt.u32.u64 %0, t; }"
        : "=r"(sbase) : "l"(dsm));

    const int tid = threadIdx.x, wid = tid >> 5, lane = tid & 31;
    const int warp_m = wid & 1;
    const int warp_n = wid >> 1;
    const int r0 = blockIdx.x * 128;
    const int K = KPARTS * 128;
    const int NCH = KPARTS * 4;

    const int q0 = tid, q1 = tid + 256;
    const int row0 = q0 >> 2, p0 = q0 & 3;
    const int row1 = q1 >> 2, p1 = q1 & 3;

    auto issue = [&](int c) {
        const __half* Ah = Ah1; const __half* Al = Al1;
        int acol = c * 32;
        if (KPARTS == 2 && c >= 4) { Ah = Ah2; Al = Al2; acol = (c - 4) * 32; }
        uint32_t st = sbase + (c & 1) * STAGE_B;
        int gr0 = r0 + row0, gr1 = r0 + row1;
        cp16(st + row0 * 96 + p0 * 16, Ah + (size_t)gr0 * F + acol + p0 * 8, gr0 < M);
        cp16(st + row1 * 96 + p1 * 16, Ah + (size_t)gr1 * F + acol + p1 * 8, gr1 < M);
        cp16(st + STG_B + row0 * 96 + p0 * 16, Al + (size_t)gr0 * F + acol + p0 * 8, gr0 < M);
        cp16(st + STG_B + row1 * 96 + p1 * 16, Al + (size_t)gr1 * F + acol + p1 * 8, gr1 < M);
        cp16(st + 2 * STG_B + row0 * 96 + p0 * 16, Wh + (size_t)row0 * K + c * 32 + p0 * 8, true);
        cp16(st + 2 * STG_B + row1 * 96 + p1 * 16, Wh + (size_t)row1 * K + c * 32 + p1 * 8, true);
        cp16(st + 3 * STG_B + row0 * 96 + p0 * 16, Wl + (size_t)row0 * K + c * 32 + p0 * 8, true);
        cp16(st + 3 * STG_B + row1 * 96 + p1 * 16, Wl + (size_t)row1 * K + c * 32 + p1 * 8, true);
        CP_COMMIT();
    };

    wmma::fragment<wmma::accumulator, 16, 16, 16, float> acc[4][2];
#pragma unroll
    for (int i = 0; i < 4; i++)
#pragma unroll
        for (int j = 0; j < 2; j++) wmma::fill_fragment(acc[i][j], 0.f);

    issue(0);

    for (int c = 0; c < NCH; ++c) {
        if (c + 1 < NCH) issue(c + 1);
        if (c + 1 < NCH) CP_WAIT1(); else CP_WAIT0();
        __syncthreads();

        const char* st = dsm + (c & 1) * STAGE_B;
        const __half (*sAh)[BKP] = (const __half(*)[BKP])(st);
        const __half (*sAl)[BKP] = (const __half(*)[BKP])(st + STG_B);
        const __half (*sWh)[BKP] = (const __half(*)[BKP])(st + 2 * STG_B);
        const __half (*sWl)[BKP] = (const __half(*)[BKP])(st + 3 * STG_B);

#pragma unroll
        for (int ks = 0; ks < 2; ks++) {
            wmma::fragment<wmma::matrix_b, 16, 16, 16, __half, wmma::col_major> bh[2], bl[2];
#pragma unroll
            for (int wn = 0; wn < 2; wn++) {
                wmma::load_matrix_sync(bh[wn], &sWh[warp_n * 32 + wn * 16][ks * 16], BKP);
                wmma::load_matrix_sync(bl[wn], &sWl[warp_n * 32 + wn * 16][ks * 16], BKP);
            }
#pragma unroll
            for (int wm = 0; wm < 4; wm++) {
                wmma::fragment<wmma::matrix_a, 16, 16, 16, __half, wmma::row_major> ah, al;
                wmma::load_matrix_sync(ah, &sAh[warp_m * 64 + wm * 16][ks * 16], BKP);
                wmma::load_matrix_sync(al, &sAl[warp_m * 64 + wm * 16][ks * 16], BKP);
#pragma unroll
                for (int wn = 0; wn < 2; wn++) {
                    wmma::mma_sync(acc[wm][wn], ah, bh[wn], acc[wm][wn]);
                    wmma::mma_sync(acc[wm][wn], ah, bl[wn], acc[wm][wn]);
                    wmma::mma_sync(acc[wm][wn], al, bh[wn], acc[wm][wn]);
                }
            }
        }
        __syncthreads();
    }

    // epilogue
#pragma unroll
    for (int wm = 0; wm < 4; wm++)
#pragma unroll
        for (int wn = 0; wn < 2; wn++) {
            wmma::store_matrix_sync(stage[wid], acc[wm][wn], 16, wmma::mem_row_major);
            __syncwarp();
            int m0 = warp_m * 64 + wm * 16;
            int n0 = warp_n * 32 + wn * 16;
#pragma unroll
            for (int e = 0; e < 8; e++) {
                int idx = e * 32 + lane;
                int row = idx >> 4, col = idx & 15;
                int gr = r0 + m0 + row;
                if (gr < M) {
                    int gc = n0 + col;
                    float v = stage[wid][idx] + (bias ? bias[gc] : 0.f);
                    C[(size_t)gr * F + gc] = fmaxf(v, 0.f);
                }
            }
            __syncwarp();
        }
}

// ---------------- CSR-bucket build (optional single-level node map) ----------------
template <bool MAPPED>
__global__ void k_bucket(const int* __restrict__ esrc, const int* __restrict__ edst,
                         int E, int M, const int* __restrict__ np)
{
    int t = blockIdx.x * blockDim.x + threadIdx.x;
    int half = E >> 1;
    if (t >= half) return;
#pragma unroll
    for (int q = 0; q < 2; q++) {
        int e = t + q * half;
        int s = esrc[e];
        int d = edst[e];
        if (MAPPED) { s = np[s]; d = np[d]; }
        if (s >= M || d >= M) continue;
        int pos = atomicAdd(&g_deg[d], 1);
        if (pos < CAPD) g_bkt[(size_t)d * CAPD + pos] = s;
    }
}

// ---------------- compose npC = npB o npA ----------------
__global__ void k_collapse(int Msrc)
{
    int v = blockIdx.x * blockDim.x + threadIdx.x;
    if (v <= Msrc) g_npC[v] = g_npB[g_npA[v]];
}

// ---------------- gather-max: warp per dst node; writes hi/lo fp16 splits ----------------
__global__ void k_aggr(const float* __restrict__ y, int M)
{
    int warp = blockIdx.x * (blockDim.x >> 5) + (threadIdx.x >> 5);
    int lane = threadIdx.x & 31;
    if (warp >= M) return;
    int dv = g_deg[warp];
    if (dv > CAPD) dv = CAPD;
    const int* b = g_bkt + (size_t)warp * CAPD;
    float4 acc = ((const float4*)(y + (size_t)warp * F))[lane];
    int i = 0;
    for (; i + 3 < dv; i += 4) {
        int s0 = b[i], s1 = b[i + 1], s2 = b[i + 2], s3 = b[i + 3];
        float4 t0 = ((const float4*)(y + (size_t)s0 * F))[lane];
        float4 t1 = ((const float4*)(y + (size_t)s1 * F))[lane];
        float4 t2 = ((const float4*)(y + (size_t)s2 * F))[lane];
        float4 t3 = ((const float4*)(y + (size_t)s3 * F))[lane];
        acc.x = fmaxf(fmaxf(acc.x, fmaxf(t0.x, t1.x)), fmaxf(t2.x, t3.x));
        acc.y = fmaxf(fmaxf(acc.y, fmaxf(t0.y, t1.y)), fmaxf(t2.y, t3.y));
        acc.z = fmaxf(fmaxf(acc.z, fmaxf(t0.z, t1.z)), fmaxf(t2.z, t3.z));
        acc.w = fmaxf(fmaxf(acc.w, fmaxf(t0.w, t1.w)), fmaxf(t2.w, t3.w));
    }
    for (; i < dv; i++) {
        int s0 = b[i];
        float4 t0 = ((const float4*)(y + (size_t)s0 * F))[lane];
        acc.x = fmaxf(acc.x, t0.x);
        acc.y = fmaxf(acc.y, t0.y);
        acc.z = fmaxf(acc.z, t0.z);
        acc.w = fmaxf(acc.w, t0.w);
    }
    __half h0, h1, h2, h3, l0, l1, l2, l3;
    split2(acc.x, h0, l0); split2(acc.y, h1, l1);
    split2(acc.z, h2, l2); split2(acc.w, h3, l3);
    __half2* oh = (__half2*)(g_ah + (size_t)warp * F + lane * 4);
    __half2* ol = (__half2*)(g_al + (size_t)warp * F + lane * 4);
    oh[0] = __halves2half2(h0, h1); oh[1] = __halves2half2(h2, h3);
    ol[0] = __halves2half2(l0, l1); ol[1] = __halves2half2(l2, l3);
}

// ---------------- scores (wnorm fused) ----------------
__global__ void k_scores(const float* __restrict__ h, const float* __restrict__ w, int M)
{
    __shared__ float s_inv;
    int lane = threadIdx.x & 31;
    if (threadIdx.x < 32) {
        float4 b0 = ((const float4*)w)[lane];
        float sq = b0.x * b0.x + b0.y * b0.y + b0.z * b0.z + b0.w * b0.w;
        for (int o = 16; o > 0; o >>= 1) sq += __shfl_down_sync(0xffffffffu, sq, o);
        if (lane == 0) s_inv = rsqrtf(sq);
    }
    __syncthreads();
    int warp = blockIdx.x * (blockDim.x >> 5) + (threadIdx.x >> 5);
    if (warp >= M) return;
    float4 a = ((const float4*)(h + (size_t)warp * F))[lane];
    float4 b = ((const float4*)w)[lane];
    float d = a.x * b.x + a.y * b.y + a.z * b.z + a.w * b.w;
    for (int o = 16; o > 0; o >>= 1) d += __shfl_down_sync(0xffffffffu, d, o);
    if (lane == 0) g_s[warp] = d * s_inv;
}

// ---------------- per-graph exact radix select (also zeroes pool counters) ----------------
__global__ __launch_bounds__(1024)
void k_select(int n, int kk)
{
    int g = blockIdx.x;
    const float* sg = g_s + (size_t)g * n;
    __shared__ unsigned hist[256];
    __shared__ unsigned s_prefix, s_mask;
    __shared__ int s_need;
    if (threadIdx.x == 0) { s_prefix = 0; s_mask = 0; s_need = kk; }
    __syncthreads();
    for (int pass = 0; pass < 4; ++pass) {
        int shift = 24 - 8 * pass;
        if (threadIdx.x < 256) hist[threadIdx.x] = 0;
        __syncthreads();
        unsigned pre = s_prefix, msk = s_mask;
        for (int i = threadIdx.x; i < n; i += blockDim.x) {
            unsigned key = ordkey(sg[i]);
            if ((key & msk) == pre) atomicAdd(&hist[(key >> shift) & 255], 1u);
        }
        __syncthreads();
        if (threadIdx.x == 0) {
            int need = s_need;
            unsigned cum = 0;
            for (int b = 255; b >= 0; --b) {
                unsigned h = hist[b];
                if (cum + h >= (unsigned)need) {
                    s_need = need - (int)cum;
                    s_prefix = pre | ((unsigned)b << shift);
                    s_mask = msk | (255u << shift);
                    break;
                }
                cum += h;
            }
        }
        __syncthreads();
    }
    if (threadIdx.x == 0) {
        g_thr[g] = s_prefix; g_needeq[g] = s_need;
        g_cnt[g] = 0; g_eqcnt[g] = 0;
    }
}

// ---------------- compact: writes full node map np (initpool fused) ----------------
__global__ void k_compact(int M, int n, int kk, int Mn, int* __restrict__ np)
{
    int v = blockIdx.x * blockDim.x + threadIdx.x;
    if (v > M) return;
    if (v == M) { np[M] = Mn; return; }
    int g = v / n;
    float sv = g_s[v];
    unsigned key = ordkey(sv);
    unsigned T = g_thr[g];
    bool keep = false;
    if (key > T) keep = true;
    else if (key == T && atomicAdd(&g_eqcnt[g], 1) < g_needeq[g]) keep = true;
    if (!keep) { np[v] = Mn; return; }
    int pos = atomicAdd(&g_cnt[g], 1);
    int j = g * kk + pos;
    np[v] = j;
    g_gidx[j] = v;
    g_tanhv[j] = tanhf(sv);
}

// ---------------- gather: float out + fp16 splits for next gemm1 ----------------
__global__ void k_gather(const float* __restrict__ h, float* __restrict__ xnew, int Mn)
{
    int idx = blockIdx.x * blockDim.x + threadIdx.x;
    int j = idx >> 5, q = idx & 31;
    if (j >= Mn) return;
    float t = g_tanhv[j];
    float4 v = *(const float4*)(h + (size_t)g_gidx[j] * F + q * 4);
    v.x *= t; v.y *= t; v.z *= t; v.w *= t;
    *(float4*)(xnew + (size_t)j * F + q * 4) = v;
    __half h0, h1, h2, h3, l0, l1, l2, l3;
    split2(v.x, h0, l0); split2(v.y, h1, l1);
    split2(v.z, h2, l2); split2(v.w, h3, l3);
    __half2* oh = (__half2*)(g_xh + (size_t)j * F + q * 4);
    __half2* ol = (__half2*)(g_xl + (size_t)j * F + q * 4);
    oh[0] = __halves2half2(h0, h1); oh[1] = __halves2half2(h2, h3);
    ol[0] = __halves2half2(l0, l1); ol[1] = __halves2half2(l2, l3);
}

// ---------------- readout ----------------
__global__ void k_rpart(const float* __restrict__ x, int kk)
{
    int g = blockIdx.x / CH, c = blockIdx.x % CH;
    int rpc = kk / CH;
    int f = threadIdx.x;  // 128
    const float* base = x + ((size_t)g * kk + (size_t)c * rpc) * F + f;
    float vmax = -3.4e38f, vsum = 0.f;
    for (int r = 0; r < rpc; r++) {
        float v = base[(size_t)r * F];
        vmax = fmaxf(vmax, v);
        vsum += v;
    }
    float* p = g_part + (size_t)blockIdx.x * 2 * F;
    p[f] = vmax;
    p[F + f] = vsum;
}

__global__ void k_rfinal(int kk, int store)
{
    int g = blockIdx.x;
    int f = threadIdx.x;  // 256
    const float* p = g_part + (size_t)g * CH * 2 * F;
    float r;
    if (f < F) {
        float m = -3.4e38f;
        for (int c = 0; c < CH; c++) m = fmaxf(m, p[c * 2 * F + f]);
        r = m;
    } else {
        float s = 0.f;
        for (int c = 0; c < CH; c++) s += p[c * 2 * F + f];
        r = s / (float)kk;
    }
    if (store) g_z[g * 2 * F + f] = r;
    else       g_z[g * 2 * F + f] += r;
}

// ---------------- final MLP + sigmoid ----------------
__global__ void k_mlp(const float* __restrict__ Wl1, const float* __restrict__ bl1,
                      const float* __restrict__ Wl2, const float* __restrict__ bl2,
                      const float* __restrict__ Wl3, const float* __restrict__ bl3,
                      float* __restrict__ out)
{
    __shared__ float sz[BGR][2 * F];
    __shared__ float h1[BGR][F];
    __shared__ float h2[BGR][64];
    int t = threadIdx.x;  // 256
    for (int i = t; i < BGR * 2 * F; i += 256) ((float*)sz)[i] = g_z[i];
    __syncthreads();
    for (int o = t; o < BGR * F; o += 256) {
        int g = o >> 7, r = o & 127;
        float a = bl1[r];
        const float* wr = Wl1 + (size_t)r * 2 * F;
        for (int c = 0; c < 2 * F; c++) a += sz[g][c] * wr[c];
        h1[g][r] = fmaxf(a, 0.f);
    }
    __syncthreads();
    for (int o = t; o < BGR * 64; o += 256) {
        int g = o >> 6, r = o & 63;
        float a = bl2[r];
        const float* wr = Wl2 + (size_t)r * F;
        for (int c = 0; c < F; c++) a += h1[g][c] * wr[c];
        h2[g][r] = fmaxf(a, 0.f);
    }
    __syncthreads();
    if (t < BGR) {
        float a = bl3[0];
        for (int c = 0; c < 64; c++) a += h2[t][c] * Wl3[c];
        out[t] = 1.f / (1.f + expf(-a));
    }
}

// ---------------- orchestration: minimal fork/join (bucket chain under gemm1) ----
extern "C" void kernel_launch(void* const* d_in, const int* in_sizes, int n_in,
                              void* d_out, int out_size)
{
    const float* x = (const float*)d_in[0];
    const int* ei = (const int*)d_in[1];
    const float* Wlin[3] = { (const float*)d_in[2], (const float*)d_in[6], (const float*)d_in[10] };
    const float* blin[3] = { (const float*)d_in[3], (const float*)d_in[7], (const float*)d_in[11] };
    const float* Wupd[3] = { (const float*)d_in[4], (const float*)d_in[8], (const float*)d_in[12] };
    const float* wp[3]   = { (const float*)d_in[5], (const float*)d_in[9], (const float*)d_in[13] };
    const float* Wl1 = (const float*)d_in[14];
    const float* bl1 = (const float*)d_in[15];
    const float* Wl2 = (const float*)d_in[16];
    const float* bl2 = (const float*)d_in[17];
    const float* Wl3 = (const float*)d_in[18];
    const float* bl3 = (const float*)d_in[19];

    float *yb, *h1p, *h2p;
    __half *xh, *xl, *ah, *al, *w1h, *w1l, *w2h, *w2l;
    int *npA, *npB, *npC;
    cudaGetSymbolAddress((void**)&yb, g_y);
    cudaGetSymbolAddress((void**)&h1p, g_h1);
    cudaGetSymbolAddress((void**)&h2p, g_h2);
    cudaGetSymbolAddress((void**)&xh, g_xh);
    cudaGetSymbolAddress((void**)&xl, g_xl);
    cudaGetSymbolAddress((void**)&ah, g_ah);
    cudaGetSymbolAddress((void**)&al, g_al);
    cudaGetSymbolAddress((void**)&w1h, g_w1h);
    cudaGetSymbolAddress((void**)&w1l, g_w1l);
    cudaGetSymbolAddress((void**)&w2h, g_w2h);
    cudaGetSymbolAddress((void**)&w2l, g_w2l);
    cudaGetSymbolAddress((void**)&npA, g_npA);
    cudaGetSymbolAddress((void**)&npB, g_npB);
    cudaGetSymbolAddress((void**)&npC, g_npC);

    static cudaEvent_t ev[8];
    static int init_done = 0;
    if (!init_done) {
        cudaFuncSetAttribute(k_gemm_h<1>, cudaFuncAttributeMaxDynamicSharedMemorySize, SMEM_H);
        cudaFuncSetAttribute(k_gemm_h<2>, cudaFuncAttributeMaxDynamicSharedMemorySize, SMEM_H);
        for (int i = 0; i < 8; i++)
            cudaEventCreateWithFlags(&ev[i], cudaEventDisableTiming);
        init_done = 1;
    }

    cudaStream_t m = 0;                    // capture (legacy default) stream
    cudaStream_t sd = cudaStreamPerThread; // side stream

    const int Ms[3] = { 100000, 80000, 64000 };
    const int kks[3] = { 10000, 8000, 6400 };

    const int* es = ei;
    const int* ed = ei + EMAX;

    // initial fork
    cudaEventRecord(ev[0], m);
    cudaStreamWaitEvent(sd, ev[0], 0);

    k_split<<<(NMAX * F / 4 + 255) / 256, 256, 0, m>>>(x, xh, xl, NMAX * F / 4);

    for (int st = 0; st < 3; ++st) {
        int M = Ms[st];
        int gridG = (M + 127) / 128;
        int kk = kks[st], n = M / BGR, Mn = BGR * kk;

        // ---- side chain: zerodeg (+collapse) + bucket, hidden under main's gemm1
        // (stage st>0 already gated on prev compact via ev[1+st-1])
        k_zerodeg<<<(M + 255) / 256, 256, 0, sd>>>(M);
        if (st == 2)
            k_collapse<<<(NMAX + 1 + 255) / 256, 256, 0, sd>>>(NMAX);
        if (st == 0)
            k_bucket<false><<<(EMAX / 2 + 255) / 256, 256, 0, sd>>>(es, ed, EMAX, M, nullptr);
        else if (st == 1)
            k_bucket<true><<<(EMAX / 2 + 255) / 256, 256, 0, sd>>>(es, ed, EMAX, M, npA);
        else
            k_bucket<true><<<(EMAX / 2 + 255) / 256, 256, 0, sd>>>(es, ed, EMAX, M, npC);
        cudaEventRecord(ev[4 + st], sd);   // evB: bucket ready

        // ---- main chain
        k_prepw<<<(128 * 384 / 4 + 255) / 256, 256, 0, m>>>(Wlin[st], Wupd[st]);
        k_gemm_h<1><<<gridG, 256, SMEM_H, m>>>(xh, xl, nullptr, nullptr, w1h, w1l,
                                               blin[st], yb, M);
        cudaStreamWaitEvent(m, ev[4 + st], 0);
        k_aggr<<<(M + 7) / 8, 256, 0, m>>>(yb, M);
        k_gemm_h<2><<<gridG, 256, SMEM_H, m>>>(ah, al, xh, xl, w2h, w2l, nullptr, h1p, M);

        k_scores<<<(M + 3) / 4, 128, 0, m>>>(h1p, wp[st], M);
        k_select<<<BGR, 1024, 0, m>>>(n, kk);
        int* npOut = (st == 0) ? npA : npB;
        k_compact<<<(M + 1 + 255) / 256, 256, 0, m>>>(M, n, kk, Mn, npOut);
        if (st < 2) {
            cudaEventRecord(ev[1 + st], m);            // evA: deg/bkt free + maps ready
            cudaStreamWaitEvent(sd, ev[1 + st], 0);    // gate next stage's side chain
        }
        k_gather<<<(Mn * 32 + 255) / 256, 256, 0, m>>>(h1p, h2p, Mn);

        k_rpart<<<BGR * CH, 128, 0, m>>>(h2p, kk);
        k_rfinal<<<BGR, 256, 0, m>>>(kk, st == 0 ? 1 : 0);
    }

    k_mlp<<<1, 256, 0, m>>>(Wl1, bl1, Wl2, bl2, Wl3, bl3, (float*)d_out);
}

// round 17
// speedup vs baseline: 1.2030x; 1.1706x over previous
#include <cuda_runtime.h>
#include <cuda_fp16.h>
#include <math.h>
#include <stdint.h>
#include <mma.h>

using namespace nvcuda;

#define F 128
#define NMAX 100000
#define EMAX 1600000
#define BGR 8
#define CH 40
#define CAPD 96
#define BKP 48

// ---------------- device scratch ----------------
__device__ float  g_y[NMAX * F];
__device__ float  g_h1[NMAX * F];
__device__ __half g_xh[NMAX * F];
__device__ __half g_xl[NMAX * F];
__device__ __half g_ah[NMAX * F];
__device__ __half g_al[NMAX * F];
__device__ __half g_w1h[3][128 * 128];
__device__ __half g_w1l[3][128 * 128];
__device__ __half g_w2h[3][128 * 256];
__device__ __half g_w2l[3][128 * 256];
__device__ int    g_npA[NMAX + 1];
__device__ int    g_npB[80001];
__device__ int    g_npC[NMAX + 1];
__device__ int    g_deg[NMAX];
__device__ int    g_bkt[NMAX * CAPD];
__device__ float  g_s[NMAX];
__device__ int    g_gidx[80000];
__device__ float  g_tanhv[80000];
__device__ float  g_z[BGR * 2 * F];
__device__ float  g_part[BGR * CH * 2 * F];

__device__ __forceinline__ unsigned ordkey(float f) {
    unsigned u = __float_as_uint(f);
    return (u & 0x80000000u) ? ~u : (u | 0x80000000u);
}

__device__ __forceinline__ void split2(float v, __half& h, __half& l) {
    h = __float2half_rn(v);
    l = __float2half_rn(v - __half2float(h));
}

__device__ __forceinline__ void cp16(uint32_t saddr, const void* gptr, bool valid) {
    int sz = valid ? 16 : 0;
    asm volatile("cp.async.cg.shared.global [%0], [%1], 16, %2;"
                 :: "r"(saddr), "l"(gptr), "r"(sz));
}
#define CP_COMMIT() asm volatile("cp.async.commit_group;" ::: "memory")
#define CP_WAIT1()  asm volatile("cp.async.wait_group 1;" ::: "memory")
#define CP_WAIT0()  asm volatile("cp.async.wait_group 0;" ::: "memory")

// ---------------- stage-0 input split ----------------
__global__ void k_split(const float* __restrict__ src, __half* __restrict__ hi,
                        __half* __restrict__ lo, int n4)
{
    int i = blockIdx.x * blockDim.x + threadIdx.x;
    if (i >= n4) return;
    float4 v = ((const float4*)src)[i];
    __half h0, h1, h2, h3, l0, l1, l2, l3;
    split2(v.x, h0, l0); split2(v.y, h1, l1);
    split2(v.z, h2, l2); split2(v.w, h3, l3);
    ((__half2*)hi)[i * 2 + 0] = __halves2half2(h0, h1);
    ((__half2*)hi)[i * 2 + 1] = __halves2half2(h2, h3);
    ((__half2*)lo)[i * 2 + 0] = __halves2half2(l0, l1);
    ((__half2*)lo)[i * 2 + 1] = __halves2half2(l2, l3);
}

// ---------------- all weight splits, once ----------------
__global__ void k_prepw_all(const float* W1a, const float* W2a,
                            const float* W1b, const float* W2b,
                            const float* W1c, const float* W2c)
{
    const int n1 = 128 * 128 / 4;   // 4096
    const int n2 = 128 * 256 / 4;   // 8192
    const int per = n1 + n2;        // 12288
    int i = blockIdx.x * blockDim.x + threadIdx.x;
    if (i >= 3 * per) return;
    int st = i / per;
    int r = i - st * per;
    const float* W1 = (st == 0) ? W1a : (st == 1) ? W1b : W1c;
    const float* W2 = (st == 0) ? W2a : (st == 1) ? W2b : W2c;
    if (r < n1) {
        float4 v = ((const float4*)W1)[r];
        __half h0, h1, h2, h3, l0, l1, l2, l3;
        split2(v.x, h0, l0); split2(v.y, h1, l1);
        split2(v.z, h2, l2); split2(v.w, h3, l3);
        ((__half2*)g_w1h[st])[r * 2 + 0] = __halves2half2(h0, h1);
        ((__half2*)g_w1h[st])[r * 2 + 1] = __halves2half2(h2, h3);
        ((__half2*)g_w1l[st])[r * 2 + 0] = __halves2half2(l0, l1);
        ((__half2*)g_w1l[st])[r * 2 + 1] = __halves2half2(l2, l3);
    } else {
        int idx = r - n1;
        float4 v = ((const float4*)W2)[idx];
        __half h0, h1, h2, h3, l0, l1, l2, l3;
        split2(v.x, h0, l0); split2(v.y, h1, l1);
        split2(v.z, h2, l2); split2(v.w, h3, l3);
        ((__half2*)g_w2h[st])[idx * 2 + 0] = __halves2half2(h0, h1);
        ((__half2*)g_w2h[st])[idx * 2 + 1] = __halves2half2(h2, h3);
        ((__half2*)g_w2l[st])[idx * 2 + 0] = __halves2half2(l0, l1);
        ((__half2*)g_w2l[st])[idx * 2 + 1] = __halves2half2(l2, l3);
    }
}

__global__ void k_zerodeg(int M)
{
    int i = blockIdx.x * blockDim.x + threadIdx.x;
    if (i < M) g_deg[i] = 0;
}

// ---------------- fp16-split wmma GEMM with cp.async double buffering ----------------
#define STG_B 12288
#define STAGE_B (4 * STG_B)
#define SMEM_H (2 * STAGE_B + 8192)

template <int KPARTS>
__global__ __launch_bounds__(256)
void k_gemm_h(const __half* __restrict__ Ah1, const __half* __restrict__ Al1,
              const __half* __restrict__ Ah2, const __half* __restrict__ Al2,
              const __half* __restrict__ Wh, const __half* __restrict__ Wl,
              const float* __restrict__ bias, float* __restrict__ C, int M)
{
    extern __shared__ __align__(16) char dsm[];
    float (*stage)[256] = (float(*)[256])(dsm + 2 * STAGE_B);
    uint32_t sbase;
    asm("{ .reg .u64 t; cvta.to.shared.u64 t, %1; cvt.u32.u64 %0, t; }"
        : "=r"(sbase) : "l"(dsm));

    const int tid = threadIdx.x, wid = tid >> 5, lane = tid & 31;
    const int warp_m = wid & 1;
    const int warp_n = wid >> 1;
    const int r0 = blockIdx.x * 128;
    const int K = KPARTS * 128;
    const int NCH = KPARTS * 4;

    const int q0 = tid, q1 = tid + 256;
    const int row0 = q0 >> 2, p0 = q0 & 3;
    const int row1 = q1 >> 2, p1 = q1 & 3;

    auto issue = [&](int c) {
        const __half* Ah = Ah1; const __half* Al = Al1;
        int acol = c * 32;
        if (KPARTS == 2 && c >= 4) { Ah = Ah2; Al = Al2; acol = (c - 4) * 32; }
        uint32_t st = sbase + (c & 1) * STAGE_B;
        int gr0 = r0 + row0, gr1 = r0 + row1;
        cp16(st + row0 * 96 + p0 * 16, Ah + (size_t)gr0 * F + acol + p0 * 8, gr0 < M);
        cp16(st + row1 * 96 + p1 * 16, Ah + (size_t)gr1 * F + acol + p1 * 8, gr1 < M);
        cp16(st + STG_B + row0 * 96 + p0 * 16, Al + (size_t)gr0 * F + acol + p0 * 8, gr0 < M);
        cp16(st + STG_B + row1 * 96 + p1 * 16, Al + (size_t)gr1 * F + acol + p1 * 8, gr1 < M);
        cp16(st + 2 * STG_B + row0 * 96 + p0 * 16, Wh + (size_t)row0 * K + c * 32 + p0 * 8, true);
        cp16(st + 2 * STG_B + row1 * 96 + p1 * 16, Wh + (size_t)row1 * K + c * 32 + p1 * 8, true);
        cp16(st + 3 * STG_B + row0 * 96 + p0 * 16, Wl + (size_t)row0 * K + c * 32 + p0 * 8, true);
        cp16(st + 3 * STG_B + row1 * 96 + p1 * 16, Wl + (size_t)row1 * K + c * 32 + p1 * 8, true);
        CP_COMMIT();
    };

    wmma::fragment<wmma::accumulator, 16, 16, 16, float> acc[4][2];
#pragma unroll
    for (int i = 0; i < 4; i++)
#pragma unroll
        for (int j = 0; j < 2; j++) wmma::fill_fragment(acc[i][j], 0.f);

    issue(0);

    for (int c = 0; c < NCH; ++c) {
        if (c + 1 < NCH) issue(c + 1);
        if (c + 1 < NCH) CP_WAIT1(); else CP_WAIT0();
        __syncthreads();

        const char* st = dsm + (c & 1) * STAGE_B;
        const __half (*sAh)[BKP] = (const __half(*)[BKP])(st);
        const __half (*sAl)[BKP] = (const __half(*)[BKP])(st + STG_B);
        const __half (*sWh)[BKP] = (const __half(*)[BKP])(st + 2 * STG_B);
        const __half (*sWl)[BKP] = (const __half(*)[BKP])(st + 3 * STG_B);

#pragma unroll
        for (int ks = 0; ks < 2; ks++) {
            wmma::fragment<wmma::matrix_b, 16, 16, 16, __half, wmma::col_major> bh[2], bl[2];
#pragma unroll
            for (int wn = 0; wn < 2; wn++) {
                wmma::load_matrix_sync(bh[wn], &sWh[warp_n * 32 + wn * 16][ks * 16], BKP);
                wmma::load_matrix_sync(bl[wn], &sWl[warp_n * 32 + wn * 16][ks * 16], BKP);
            }
#pragma unroll
            for (int wm = 0; wm < 4; wm++) {
                wmma::fragment<wmma::matrix_a, 16, 16, 16, __half, wmma::row_major> ah, al;
                wmma::load_matrix_sync(ah, &sAh[warp_m * 64 + wm * 16][ks * 16], BKP);
                wmma::load_matrix_sync(al, &sAl[warp_m * 64 + wm * 16][ks * 16], BKP);
#pragma unroll
                for (int wn = 0; wn < 2; wn++) {
                    wmma::mma_sync(acc[wm][wn], ah, bh[wn], acc[wm][wn]);
                    wmma::mma_sync(acc[wm][wn], ah, bl[wn], acc[wm][wn]);
                    wmma::mma_sync(acc[wm][wn], al, bh[wn], acc[wm][wn]);
                }
            }
        }
        __syncthreads();
    }

    // epilogue
#pragma unroll
    for (int wm = 0; wm < 4; wm++)
#pragma unroll
        for (int wn = 0; wn < 2; wn++) {
            wmma::store_matrix_sync(stage[wid], acc[wm][wn], 16, wmma::mem_row_major);
            __syncwarp();
            int m0 = warp_m * 64 + wm * 16;
            int n0 = warp_n * 32 + wn * 16;
#pragma unroll
            for (int e = 0; e < 8; e++) {
                int idx = e * 32 + lane;
                int row = idx >> 4, col = idx & 15;
                int gr = r0 + m0 + row;
                if (gr < M) {
                    int gc = n0 + col;
                    float v = stage[wid][idx] + (bias ? bias[gc] : 0.f);
                    C[(size_t)gr * F + gc] = fmaxf(v, 0.f);
                }
            }
            __syncwarp();
        }
}

// ---------------- CSR-bucket build (optional single-level node map) ----------------
template <bool MAPPED>
__global__ void k_bucket(const int* __restrict__ esrc, const int* __restrict__ edst,
                         int E, int M, const int* __restrict__ np)
{
    int t = blockIdx.x * blockDim.x + threadIdx.x;
    int half = E >> 1;
    if (t >= half) return;
#pragma unroll
    for (int q = 0; q < 2; q++) {
        int e = t + q * half;
        int s = esrc[e];
        int d = edst[e];
        if (MAPPED) { s = np[s]; d = np[d]; }
        if (s >= M || d >= M) continue;
        int pos = atomicAdd(&g_deg[d], 1);
        if (pos < CAPD) g_bkt[(size_t)d * CAPD + pos] = s;
    }
}

// ---------------- compose npC = npB o npA ----------------
__global__ void k_collapse(int Msrc)
{
    int v = blockIdx.x * blockDim.x + threadIdx.x;
    if (v <= Msrc) g_npC[v] = g_npB[g_npA[v]];
}

// ---------------- gather-max: warp per dst node; writes hi/lo fp16 splits ----------------
__global__ void k_aggr(const float* __restrict__ y, int M)
{
    int warp = blockIdx.x * (blockDim.x >> 5) + (threadIdx.x >> 5);
    int lane = threadIdx.x & 31;
    if (warp >= M) return;
    int dv = g_deg[warp];
    if (dv > CAPD) dv = CAPD;
    const int* b = g_bkt + (size_t)warp * CAPD;
    float4 acc = ((const float4*)(y + (size_t)warp * F))[lane];
    int i = 0;
    for (; i + 3 < dv; i += 4) {
        int s0 = b[i], s1 = b[i + 1], s2 = b[i + 2], s3 = b[i + 3];
        float4 t0 = ((const float4*)(y + (size_t)s0 * F))[lane];
        float4 t1 = ((const float4*)(y + (size_t)s1 * F))[lane];
        float4 t2 = ((const float4*)(y + (size_t)s2 * F))[lane];
        float4 t3 = ((const float4*)(y + (size_t)s3 * F))[lane];
        acc.x = fmaxf(fmaxf(acc.x, fmaxf(t0.x, t1.x)), fmaxf(t2.x, t3.x));
        acc.y = fmaxf(fmaxf(acc.y, fmaxf(t0.y, t1.y)), fmaxf(t2.y, t3.y));
        acc.z = fmaxf(fmaxf(acc.z, fmaxf(t0.z, t1.z)), fmaxf(t2.z, t3.z));
        acc.w = fmaxf(fmaxf(acc.w, fmaxf(t0.w, t1.w)), fmaxf(t2.w, t3.w));
    }
    for (; i < dv; i++) {
        int s0 = b[i];
        float4 t0 = ((const float4*)(y + (size_t)s0 * F))[lane];
        acc.x = fmaxf(acc.x, t0.x);
        acc.y = fmaxf(acc.y, t0.y);
        acc.z = fmaxf(acc.z, t0.z);
        acc.w = fmaxf(acc.w, t0.w);
    }
    __half h0, h1, h2, h3, l0, l1, l2, l3;
    split2(acc.x, h0, l0); split2(acc.y, h1, l1);
    split2(acc.z, h2, l2); split2(acc.w, h3, l3);
    __half2* oh = (__half2*)(g_ah + (size_t)warp * F + lane * 4);
    __half2* ol = (__half2*)(g_al + (size_t)warp * F + lane * 4);
    oh[0] = __halves2half2(h0, h1); oh[1] = __halves2half2(h2, h3);
    ol[0] = __halves2half2(l0, l1); ol[1] = __halves2half2(l2, l3);
}

// ---------------- scores (wnorm fused) ----------------
__global__ void k_scores(const float* __restrict__ h, const float* __restrict__ w, int M)
{
    __shared__ float s_inv;
    int lane = threadIdx.x & 31;
    if (threadIdx.x < 32) {
        float4 b0 = ((const float4*)w)[lane];
        float sq = b0.x * b0.x + b0.y * b0.y + b0.z * b0.z + b0.w * b0.w;
        for (int o = 16; o > 0; o >>= 1) sq += __shfl_down_sync(0xffffffffu, sq, o);
        if (lane == 0) s_inv = rsqrtf(sq);
    }
    __syncthreads();
    int warp = blockIdx.x * (blockDim.x >> 5) + (threadIdx.x >> 5);
    if (warp >= M) return;
    float4 a = ((const float4*)(h + (size_t)warp * F))[lane];
    float4 b = ((const float4*)w)[lane];
    float d = a.x * b.x + a.y * b.y + a.z * b.z + a.w * b.w;
    for (int o = 16; o > 0; o >>= 1) d += __shfl_down_sync(0xffffffffu, d, o);
    if (lane == 0) g_s[warp] = d * s_inv;
}

// ---------------- fused select + compact (block per graph, smem counters) ----------
__global__ __launch_bounds__(1024)
void k_selcomp(int n, int kk, int M, int Mn, int* __restrict__ np)
{
    int g = blockIdx.x;
    const float* sg = g_s + (size_t)g * n;
    __shared__ unsigned hist[256];
    __shared__ unsigned s_prefix, s_mask;
    __shared__ int s_need, s_cnt, s_eq;
    if (threadIdx.x == 0) { s_prefix = 0; s_mask = 0; s_need = kk; s_cnt = 0; s_eq = 0; }
    __syncthreads();
    for (int pass = 0; pass < 4; ++pass) {
        int shift = 24 - 8 * pass;
        if (threadIdx.x < 256) hist[threadIdx.x] = 0;
        __syncthreads();
        unsigned pre = s_prefix, msk = s_mask;
        for (int i = threadIdx.x; i < n; i += blockDim.x) {
            unsigned key = ordkey(sg[i]);
            if ((key & msk) == pre) atomicAdd(&hist[(key >> shift) & 255], 1u);
        }
        __syncthreads();
        if (threadIdx.x == 0) {
            int need = s_need;
            unsigned cum = 0;
            for (int b = 255; b >= 0; --b) {
                unsigned h = hist[b];
                if (cum + h >= (unsigned)need) {
                    s_need = need - (int)cum;
                    s_prefix = pre | ((unsigned)b << shift);
                    s_mask = msk | (255u << shift);
                    break;
                }
                cum += h;
            }
        }
        __syncthreads();
    }
    // compact this graph's slice
    unsigned T = s_prefix;
    int needeq = s_need;
    for (int i = threadIdx.x; i < n; i += blockDim.x) {
        int v = g * n + i;
        float sv = sg[i];
        unsigned key = ordkey(sv);
        bool keep = false;
        if (key > T) keep = true;
        else if (key == T && atomicAdd(&s_eq, 1) < needeq) keep = true;
        if (!keep) { np[v] = Mn; continue; }
        int pos = atomicAdd(&s_cnt, 1);
        int j = g * kk + pos;
        np[v] = j;
        g_gidx[j] = v;
        g_tanhv[j] = tanhf(sv);
    }
    if (g == 0 && threadIdx.x == 0) np[M] = Mn;
}

// ---------------- gather: writes fp16 splits only (no fp32 copy) ----------------
__global__ void k_gather(const float* __restrict__ h, int Mn)
{
    int idx = blockIdx.x * blockDim.x + threadIdx.x;
    int j = idx >> 5, q = idx & 31;
    if (j >= Mn) return;
    float t = g_tanhv[j];
    float4 v = *(const float4*)(h + (size_t)g_gidx[j] * F + q * 4);
    v.x *= t; v.y *= t; v.z *= t; v.w *= t;
    __half h0, h1, h2, h3, l0, l1, l2, l3;
    split2(v.x, h0, l0); split2(v.y, h1, l1);
    split2(v.z, h2, l2); split2(v.w, h3, l3);
    __half2* oh = (__half2*)(g_xh + (size_t)j * F + q * 4);
    __half2* ol = (__half2*)(g_xl + (size_t)j * F + q * 4);
    oh[0] = __halves2half2(h0, h1); oh[1] = __halves2half2(h2, h3);
    ol[0] = __halves2half2(l0, l1); ol[1] = __halves2half2(l2, l3);
}

// ---------------- readout partials from fp16 splits ----------------
__global__ void k_rpart(int kk)
{
    int g = blockIdx.x / CH, c = blockIdx.x % CH;
    int rpc = kk / CH;
    int f = threadIdx.x;  // 128
    size_t base = ((size_t)g * kk + (size_t)c * rpc) * F + f;
    float vmax = -3.4e38f, vsum = 0.f;
    for (int r = 0; r < rpc; r++) {
        size_t o = base + (size_t)r * F;
        float v = __half2float(g_xh[o]) + __half2float(g_xl[o]);
        vmax = fmaxf(vmax, v);
        vsum += v;
    }
    float* p = g_part + (size_t)blockIdx.x * 2 * F;
    p[f] = vmax;
    p[F + f] = vsum;
}

__global__ void k_rfinal(int kk, int store)
{
    int g = blockIdx.x;
    int f = threadIdx.x;  // 256
    const float* p = g_part + (size_t)g * CH * 2 * F;
    float r;
    if (f < F) {
        float m = -3.4e38f;
        for (int c = 0; c < CH; c++) m = fmaxf(m, p[c * 2 * F + f]);
        r = m;
    } else {
        float s = 0.f;
        for (int c = 0; c < CH; c++) s += p[c * 2 * F + f];
        r = s / (float)kk;
    }
    if (store) g_z[g * 2 * F + f] = r;
    else       g_z[g * 2 * F + f] += r;
}

// ---------------- final MLP + sigmoid ----------------
__global__ void k_mlp(const float* __restrict__ Wl1, const float* __restrict__ bl1,
                      const float* __restrict__ Wl2, const float* __restrict__ bl2,
                      const float* __restrict__ Wl3, const float* __restrict__ bl3,
                      float* __restrict__ out)
{
    __shared__ float sz[BGR][2 * F];
    __shared__ float h1[BGR][F];
    __shared__ float h2[BGR][64];
    int t = threadIdx.x;  // 256
    for (int i = t; i < BGR * 2 * F; i += 256) ((float*)sz)[i] = g_z[i];
    __syncthreads();
    for (int o = t; o < BGR * F; o += 256) {
        int g = o >> 7, r = o & 127;
        float a = bl1[r];
        const float* wr = Wl1 + (size_t)r * 2 * F;
        for (int c = 0; c < 2 * F; c++) a += sz[g][c] * wr[c];
        h1[g][r] = fmaxf(a, 0.f);
    }
    __syncthreads();
    for (int o = t; o < BGR * 64; o += 256) {
        int g = o >> 6, r = o & 63;
        float a = bl2[r];
        const float* wr = Wl2 + (size_t)r * F;
        for (int c = 0; c < F; c++) a += h1[g][c] * wr[c];
        h2[g][r] = fmaxf(a, 0.f);
    }
    __syncthreads();
    if (t < BGR) {
        float a = bl3[0];
        for (int c = 0; c < 64; c++) a += h2[t][c] * Wl3[c];
        out[t] = 1.f / (1.f + expf(-a));
    }
}

// ---------------- orchestration (serial stream) ----------------
extern "C" void kernel_launch(void* const* d_in, const int* in_sizes, int n_in,
                              void* d_out, int out_size)
{
    const float* x = (const float*)d_in[0];
    const int* ei = (const int*)d_in[1];
    const float* Wlin[3] = { (const float*)d_in[2], (const float*)d_in[6], (const float*)d_in[10] };
    const float* blin[3] = { (const float*)d_in[3], (const float*)d_in[7], (const float*)d_in[11] };
    const float* Wupd[3] = { (const float*)d_in[4], (const float*)d_in[8], (const float*)d_in[12] };
    const float* wp[3]   = { (const float*)d_in[5], (const float*)d_in[9], (const float*)d_in[13] };
    const float* Wl1 = (const float*)d_in[14];
    const float* bl1 = (const float*)d_in[15];
    const float* Wl2 = (const float*)d_in[16];
    const float* bl2 = (const float*)d_in[17];
    const float* Wl3 = (const float*)d_in[18];
    const float* bl3 = (const float*)d_in[19];

    float *yb, *h1p;
    __half *xh, *xl, *ah, *al;
    __half *w1h[3], *w1l[3], *w2h[3], *w2l[3];
    int *npA, *npB, *npC;
    cudaGetSymbolAddress((void**)&yb, g_y);
    cudaGetSymbolAddress((void**)&h1p, g_h1);
    cudaGetSymbolAddress((void**)&xh, g_xh);
    cudaGetSymbolAddress((void**)&xl, g_xl);
    cudaGetSymbolAddress((void**)&ah, g_ah);
    cudaGetSymbolAddress((void**)&al, g_al);
    {
        __half* base;
        cudaGetSymbolAddress((void**)&base, g_w1h);
        for (int s = 0; s < 3; s++) w1h[s] = base + (size_t)s * 128 * 128;
        cudaGetSymbolAddress((void**)&base, g_w1l);
        for (int s = 0; s < 3; s++) w1l[s] = base + (size_t)s * 128 * 128;
        cudaGetSymbolAddress((void**)&base, g_w2h);
        for (int s = 0; s < 3; s++) w2h[s] = base + (size_t)s * 128 * 256;
        cudaGetSymbolAddress((void**)&base, g_w2l);
        for (int s = 0; s < 3; s++) w2l[s] = base + (size_t)s * 128 * 256;
    }
    cudaGetSymbolAddress((void**)&npA, g_npA);
    cudaGetSymbolAddress((void**)&npB, g_npB);
    cudaGetSymbolAddress((void**)&npC, g_npC);

    static int init_done = 0;
    if (!init_done) {
        cudaFuncSetAttribute(k_gemm_h<1>, cudaFuncAttributeMaxDynamicSharedMemorySize, SMEM_H);
        cudaFuncSetAttribute(k_gemm_h<2>, cudaFuncAttributeMaxDynamicSharedMemorySize, SMEM_H);
        init_done = 1;
    }

    const int Ms[3] = { 100000, 80000, 64000 };
    const int kks[3] = { 10000, 8000, 6400 };

    const int* es = ei;
    const int* ed = ei + EMAX;

    k_split<<<(NMAX * F / 4 + 255) / 256, 256>>>(x, xh, xl, NMAX * F / 4);
    k_prepw_all<<<(3 * 12288 + 255) / 256, 256>>>(Wlin[0], Wupd[0], Wlin[1], Wupd[1],
                                                  Wlin[2], Wupd[2]);

    for (int st = 0; st < 3; ++st) {
        int M = Ms[st];
        int gridG = (M + 127) / 128;
        int kk = kks[st], n = M / BGR, Mn = BGR * kk;

        k_zerodeg<<<(M + 255) / 256, 256>>>(M);
        if (st == 2)
            k_collapse<<<(NMAX + 1 + 255) / 256, 256>>>(NMAX);

        // SAGEConv
        k_gemm_h<1><<<gridG, 256, SMEM_H>>>(xh, xl, nullptr, nullptr, w1h[st], w1l[st],
                                            blin[st], yb, M);
        if (st == 0)
            k_bucket<false><<<(EMAX / 2 + 255) / 256, 256>>>(es, ed, EMAX, M, nullptr);
        else if (st == 1)
            k_bucket<true><<<(EMAX / 2 + 255) / 256, 256>>>(es, ed, EMAX, M, npA);
        else
            k_bucket<true><<<(EMAX / 2 + 255) / 256, 256>>>(es, ed, EMAX, M, npC);
        k_aggr<<<(M + 7) / 8, 256>>>(yb, M);
        k_gemm_h<2><<<gridG, 256, SMEM_H>>>(ah, al, xh, xl, w2h[st], w2l[st],
                                            nullptr, h1p, M);

        // TopK pool (select + compact fused)
        k_scores<<<(M + 3) / 4, 128>>>(h1p, wp[st], M);
        int* npOut = (st == 0) ? npA : npB;
        k_selcomp<<<BGR, 1024>>>(n, kk, M, Mn, npOut);
        k_gather<<<(Mn * 32 + 255) / 256, 256>>>(h1p, Mn);

        // readout
        k_rpart<<<BGR * CH, 128>>>(kk);
        k_rfinal<<<BGR, 256>>>(kk, st == 0 ? 1 : 0);
    }

    k_mlp<<<1, 256>>>(Wl1, bl1, Wl2, bl2, Wl3, bl3, (float*)d_out);
}